// round 1
// baseline (speedup 1.0000x reference)
#include <cuda_runtime.h>
#include <cuda_bf16.h>
#include <math.h>

// ---------------------------------------------------------------------------
// Problem constants
// ---------------------------------------------------------------------------
#define BB    4
#define TT    128
#define FRR   64
#define LL    8192            // TT*FRR
#define DIMM  384
#define NHEAD 12
#define HDIM  32
#define NTOK  (BB*LL)         // 32768
#define QKVN  (3*DIMM)        // 1152
#define FFN   (4*DIMM)        // 1536

// ---------------------------------------------------------------------------
// Scratch (device globals; allocation in kernel_launch is forbidden)
// ---------------------------------------------------------------------------
__device__ float g_xs  [(size_t)NTOK * DIMM];   // residual stream (tok, 384)
__device__ float g_xn  [(size_t)NTOK * DIMM];   // rms(xs, n1)
__device__ float g_qkv [(size_t)NTOK * QKVN];   // qkv (tok, 1152)
__device__ float g_ysum[(size_t)NTOK * DIMM];   // y1+y2+y3
__device__ float g_h   [(size_t)NTOK * DIMM];   // rms(xs, n2)
__device__ float g_h1  [(size_t)NTOK * FFN];    // gelu(h@w1+b1)

// ---------------------------------------------------------------------------
// Batched 2D transpose: in (batch, rows, cols) -> out (batch, cols, rows)
// ---------------------------------------------------------------------------
__global__ void transpose_kernel(const float* __restrict__ in,
                                 float* __restrict__ out,
                                 int rows, int cols) {
    __shared__ float tile[32][33];
    int bx = blockIdx.x * 32;    // col base
    int by = blockIdx.y * 32;    // row base
    size_t plane = (size_t)rows * cols;
    const float* inb = in + (size_t)blockIdx.z * plane;
    float* outb      = out + (size_t)blockIdx.z * plane;
    int tx = threadIdx.x, ty = threadIdx.y;
    #pragma unroll
    for (int i = 0; i < 32; i += 8)
        tile[ty + i][tx] = inb[(size_t)(by + ty + i) * cols + bx + tx];
    __syncthreads();
    #pragma unroll
    for (int i = 0; i < 32; i += 8)
        outb[(size_t)(bx + ty + i) * rows + by + tx] = tile[tx][ty + i];
}

// ---------------------------------------------------------------------------
// RMS norm over DIMM=384: one block (128 threads) per token
// ---------------------------------------------------------------------------
__global__ void rms_kernel(const float* __restrict__ in,
                           const float* __restrict__ scale,
                           float* __restrict__ out) {
    int tok = blockIdx.x;
    int tid = threadIdx.x;
    const float* row = in + (size_t)tok * DIMM;
    float v0 = row[tid], v1 = row[tid + 128], v2 = row[tid + 256];
    float s = v0*v0 + v1*v1 + v2*v2;
    // block reduce (128 threads = 4 warps)
    #pragma unroll
    for (int off = 16; off > 0; off >>= 1)
        s += __shfl_down_sync(0xffffffffu, s, off);
    __shared__ float red[4];
    if ((tid & 31) == 0) red[tid >> 5] = s;
    __syncthreads();
    if (tid == 0) {
        float t = red[0] + red[1] + red[2] + red[3];
        red[0] = rsqrtf(t * (1.0f / DIMM) + 1e-6f);
    }
    __syncthreads();
    float rinv = red[0];
    float* orow = out + (size_t)tok * DIMM;
    orow[tid]       = v0 * rinv * scale[tid];
    orow[tid + 128] = v1 * rinv * scale[tid + 128];
    orow[tid + 256] = v2 * rinv * scale[tid + 256];
}

// ---------------------------------------------------------------------------
// QK rms-norm + RoPE (in-place on g_qkv). One block (384 threads) per token.
// ---------------------------------------------------------------------------
__global__ void qkrope_kernel(float* __restrict__ qkv,
                              const float* __restrict__ nq,
                              const float* __restrict__ nk,
                              const float* __restrict__ cosT,
                              const float* __restrict__ sinT) {
    int tok = blockIdx.x;
    int tid = threadIdx.x;
    size_t base = (size_t)tok * QKVN;
    float qv = qkv[base + tid];
    float kv = qkv[base + 384 + tid];
    float s2q = qv * qv, s2k = kv * kv;
    #pragma unroll
    for (int off = 16; off > 0; off >>= 1) {
        s2q += __shfl_down_sync(0xffffffffu, s2q, off);
        s2k += __shfl_down_sync(0xffffffffu, s2k, off);
    }
    __shared__ float rq[12], rk[12];
    __shared__ float sq[384], sk[384];
    int wid = tid >> 5;
    if ((tid & 31) == 0) { rq[wid] = s2q; rk[wid] = s2k; }
    __syncthreads();
    if (tid == 0) {
        float a = 0.f, b = 0.f;
        #pragma unroll
        for (int w = 0; w < 12; w++) { a += rq[w]; b += rk[w]; }
        rq[0] = rsqrtf(a * (1.0f / DIMM) + 1e-6f);
        rk[0] = rsqrtf(b * (1.0f / DIMM) + 1e-6f);
    }
    __syncthreads();
    float rinvq = rq[0], rinvk = rk[0];
    sq[tid] = qv * rinvq * nq[tid];
    sk[tid] = kv * rinvk * nk[tid];
    __syncthreads();
    int l = tok & (LL - 1);   // token position within L
    if (tid < 192) {
        int p = tid, hh = p >> 4, j = p & 15;
        int i0 = hh * HDIM + 2 * j;
        float c = cosT[l * 16 + j], s = sinT[l * 16 + j];
        float x0 = sq[i0], x1 = sq[i0 + 1];
        qkv[base + i0]     = x0 * c - x1 * s;
        qkv[base + i0 + 1] = x0 * s + x1 * c;
    } else {
        int p = tid - 192, hh = p >> 4, j = p & 15;
        int i0 = hh * HDIM + 2 * j;
        float c = cosT[l * 16 + j], s = sinT[l * 16 + j];
        float x0 = sk[i0], x1 = sk[i0 + 1];
        qkv[base + 384 + i0]     = x0 * c - x1 * s;
        qkv[base + 384 + i0 + 1] = x0 * s + x1 * c;
    }
}

// ---------------------------------------------------------------------------
// Attention. One CTA per (group, head); blockDim = S (sequence length).
// VAR 0: time-attn  (groups B*T=512,  S=64)
// VAR 1: freq-attn  (groups B*FR=256, S=128)
// VAR 2: block-attn (groups B*T1*F1=1024, S=32)
// ---------------------------------------------------------------------------
template <int VAR>
__device__ __forceinline__ int tok_of(int g, int s) {
    if (VAR == 0) { int b = g >> 7, t = g & 127; return b * LL + t * FRR + s; }
    if (VAR == 1) { int b = g >> 6, fr = g & 63; return b * LL + s * FRR + fr; }
    int b = g >> 8, r = g & 255;
    int t1 = r >> 3, f1 = r & 7;
    int t2 = s >> 3, f2 = s & 7;
    return b * LL + (t1 * 4 + t2) * FRR + f1 * 8 + f2;
}

template <int VAR, int S, bool ACC>
__global__ void attn_kernel(const float* __restrict__ qkv,
                            float* __restrict__ ysum) {
    __shared__ float Ks[S][HDIM];
    __shared__ float Vs[S][HDIM];
    int g = blockIdx.x, h = blockIdx.y, tid = threadIdx.x;

    // cooperative, coalesced load of K and V (one 128B row per 32 lanes)
    for (int idx = tid; idx < S * HDIM; idx += S) {
        int r = idx >> 5, d = idx & 31;
        size_t base = (size_t)tok_of<VAR>(g, r) * QKVN + h * HDIM;
        Ks[r][d] = qkv[base + 384 + d];
        Vs[r][d] = qkv[base + 768 + d];
    }
    // per-thread Q row (contiguous 128B => full sectors)
    size_t qbase = (size_t)tok_of<VAR>(g, tid) * QKVN + h * HDIM;
    float q[HDIM];
    #pragma unroll
    for (int d4 = 0; d4 < 8; d4++) {
        float4 v = *(const float4*)(qkv + qbase + d4 * 4);
        q[d4*4+0] = v.x; q[d4*4+1] = v.y; q[d4*4+2] = v.z; q[d4*4+3] = v.w;
    }
    __syncthreads();

    const float rscale = 0.17677669529663687f;  // 1/sqrt(32)
    float m = -1e30f, lsum = 0.f;
    float acc[HDIM];
    #pragma unroll
    for (int d = 0; d < HDIM; d++) acc[d] = 0.f;

    for (int j = 0; j < S; j++) {
        float s = 0.f;
        #pragma unroll
        for (int d = 0; d < HDIM; d++) s += q[d] * Ks[j][d];
        s *= rscale;
        float mn = fmaxf(m, s);
        float corr = __expf(m - mn);
        float p = __expf(s - mn);
        lsum = lsum * corr + p;
        #pragma unroll
        for (int d = 0; d < HDIM; d++) acc[d] = acc[d] * corr + p * Vs[j][d];
        m = mn;
    }
    float inv = 1.f / lsum;
    size_t obase = (size_t)tok_of<VAR>(g, tid) * DIMM + h * HDIM;
    #pragma unroll
    for (int d = 0; d < HDIM; d++) {
        if (ACC) ysum[obase + d] += acc[d] * inv;
        else     ysum[obase + d]  = acc[d] * inv;
    }
}

// ---------------------------------------------------------------------------
// SGEMM: C(M,N) = epi(A(M,K) @ B(K,N) + bias)
// 128x128 tile, BK=8, 256 threads, 8x8 per thread.
// EPI 0: store; EPI 1: gelu(tanh) store; EPI 2: C += (residual accumulate)
// All of M,N,K divide the tile sizes for every call here (no guards).
// ---------------------------------------------------------------------------
__device__ __forceinline__ float gelu_tanh(float x) {
    float c = 0.7978845608028654f;
    float t = tanhf(c * (x + 0.044715f * x * x * x));
    return 0.5f * x * (1.0f + t);
}

template <int EPI>
__global__ __launch_bounds__(256)
void sgemm_kernel(const float* __restrict__ A, const float* __restrict__ B,
                  const float* __restrict__ bias, float* __restrict__ C,
                  int M, int N, int K) {
    __shared__ float As[8][128];
    __shared__ float Bs[8][128];
    int tid = threadIdx.x;
    int n0 = blockIdx.x * 128, m0 = blockIdx.y * 128;
    int tx = tid & 15, ty = tid >> 4;

    float acc[8][8];
    #pragma unroll
    for (int i = 0; i < 8; i++)
        #pragma unroll
        for (int j = 0; j < 8; j++) acc[i][j] = 0.f;

    int ar = tid >> 1;          // 0..127 (A tile row)
    int ac = (tid & 1) * 4;     // 0 or 4 (A tile col, float4)
    int br = tid >> 5;          // 0..7   (B tile row)
    int bc = (tid & 31) * 4;    // 0..124 (B tile col, float4)
    const float* Aptr = A + (size_t)(m0 + ar) * K + ac;
    const float* Bptr = B + (size_t)br * N + n0 + bc;

    for (int k0 = 0; k0 < K; k0 += 8) {
        float4 av = *(const float4*)(Aptr + k0);
        float4 bv = *(const float4*)(Bptr + (size_t)k0 * N);
        As[ac + 0][ar] = av.x; As[ac + 1][ar] = av.y;
        As[ac + 2][ar] = av.z; As[ac + 3][ar] = av.w;
        *(float4*)&Bs[br][bc] = bv;
        __syncthreads();
        #pragma unroll
        for (int k = 0; k < 8; k++) {
            float a[8], b[8];
            *(float4*)(a)     = *(const float4*)&As[k][ty * 8];
            *(float4*)(a + 4) = *(const float4*)&As[k][ty * 8 + 4];
            *(float4*)(b)     = *(const float4*)&Bs[k][tx * 8];
            *(float4*)(b + 4) = *(const float4*)&Bs[k][tx * 8 + 4];
            #pragma unroll
            for (int i = 0; i < 8; i++)
                #pragma unroll
                for (int j = 0; j < 8; j++) acc[i][j] += a[i] * b[j];
        }
        __syncthreads();
    }

    #pragma unroll
    for (int i = 0; i < 8; i++) {
        int cm = m0 + ty * 8 + i;
        #pragma unroll
        for (int j = 0; j < 8; j++) {
            int cn = n0 + tx * 8 + j;
            float v = acc[i][j] + bias[cn];
            size_t idx = (size_t)cm * N + cn;
            if (EPI == 0)      C[idx] = v;
            else if (EPI == 1) C[idx] = gelu_tanh(v);
            else               C[idx] = C[idx] + v;
        }
    }
}

// ---------------------------------------------------------------------------
// kernel_launch
// Inputs: x, cos, sin, qkv_w, qkv_b, nq_s, nk_s, proj_w, proj_b,
//         n1_s, n2_s, w1, b1, w2, b2
// ---------------------------------------------------------------------------
extern "C" void kernel_launch(void* const* d_in, const int* in_sizes, int n_in,
                              void* d_out, int out_size) {
    const float* x      = (const float*)d_in[0];
    const float* cosT   = (const float*)d_in[1];
    const float* sinT   = (const float*)d_in[2];
    const float* qkv_w  = (const float*)d_in[3];
    const float* qkv_b  = (const float*)d_in[4];
    const float* nq_s   = (const float*)d_in[5];
    const float* nk_s   = (const float*)d_in[6];
    const float* proj_w = (const float*)d_in[7];
    const float* proj_b = (const float*)d_in[8];
    const float* n1_s   = (const float*)d_in[9];
    const float* n2_s   = (const float*)d_in[10];
    const float* w1     = (const float*)d_in[11];
    const float* b1     = (const float*)d_in[12];
    const float* w2     = (const float*)d_in[13];
    const float* b2     = (const float*)d_in[14];
    float* out = (float*)d_out;

    float *xs, *xn, *qkv, *ysum, *h, *h1;
    cudaGetSymbolAddress((void**)&xs,   g_xs);
    cudaGetSymbolAddress((void**)&xn,   g_xn);
    cudaGetSymbolAddress((void**)&qkv,  g_qkv);
    cudaGetSymbolAddress((void**)&ysum, g_ysum);
    cudaGetSymbolAddress((void**)&h,    g_h);
    cudaGetSymbolAddress((void**)&h1,   g_h1);

    dim3 tb(32, 8);

    // 1) x (B, DIM, L) -> xs (B, L, DIM)
    transpose_kernel<<<dim3(LL / 32, DIMM / 32, BB), tb>>>(x, xs, DIMM, LL);

    // 2) xn = rms(xs, n1_s)
    rms_kernel<<<NTOK, 128>>>(xs, n1_s, xn);

    // 3) qkv = xn @ qkv_w + qkv_b
    sgemm_kernel<0><<<dim3(QKVN / 128, NTOK / 128), 256>>>(xn, qkv_w, qkv_b,
                                                           qkv, NTOK, QKVN, DIMM);

    // 4) q/k rmsnorm + rope (in-place)
    qkrope_kernel<<<NTOK, 384>>>(qkv, nq_s, nk_s, cosT, sinT);

    // 5-7) three attentions, summed into ysum
    attn_kernel<0, 64,  false><<<dim3(BB * TT,  NHEAD), 64 >>>(qkv, ysum);
    attn_kernel<1, 128, true ><<<dim3(BB * FRR, NHEAD), 128>>>(qkv, ysum);
    attn_kernel<2, 32,  true ><<<dim3(BB * 256, NHEAD), 32 >>>(qkv, ysum);

    // 8) xs += ysum @ proj_w + proj_b
    sgemm_kernel<2><<<dim3(DIMM / 128, NTOK / 128), 256>>>(ysum, proj_w, proj_b,
                                                           xs, NTOK, DIMM, DIMM);

    // 9) h = rms(xs, n2_s)
    rms_kernel<<<NTOK, 128>>>(xs, n2_s, h);

    // 10) h1 = gelu(h @ w1 + b1)
    sgemm_kernel<1><<<dim3(FFN / 128, NTOK / 128), 256>>>(h, w1, b1,
                                                          h1, NTOK, FFN, DIMM);

    // 11) xs += h1 @ w2 + b2
    sgemm_kernel<2><<<dim3(DIMM / 128, NTOK / 128), 256>>>(h1, w2, b2,
                                                           xs, NTOK, DIMM, FFN);

    // 12) xs (B, L, DIM) -> out (B, DIM, L)
    transpose_kernel<<<dim3(DIMM / 32, LL / 32, BB), tb>>>(xs, out, LL, DIMM);
}

// round 3
// speedup vs baseline: 2.0725x; 2.0725x over previous
#include <cuda_runtime.h>
#include <cuda_bf16.h>
#include <math.h>

// ---------------------------------------------------------------------------
// Problem constants
// ---------------------------------------------------------------------------
#define BB    4
#define TT    128
#define FRR   64
#define LL    8192            // TT*FRR
#define DIMM  384
#define NHEAD 12
#define HDIM  32
#define NTOK  (BB*LL)         // 32768
#define QKVN  (3*DIMM)        // 1152
#define FFN   (4*DIMM)        // 1536

// ---------------------------------------------------------------------------
// Scratch (device globals; allocation in kernel_launch is forbidden)
// ---------------------------------------------------------------------------
__device__ float g_xs  [(size_t)NTOK * DIMM];
__device__ float g_xn  [(size_t)NTOK * DIMM];
__device__ float g_qkv [(size_t)NTOK * QKVN];
__device__ float g_ysum[(size_t)NTOK * DIMM];
__device__ float g_h   [(size_t)NTOK * DIMM];
__device__ float g_h1  [(size_t)NTOK * FFN];

// ---------------------------------------------------------------------------
// Batched 2D transpose: in (batch, rows, cols) -> out (batch, cols, rows)
// ---------------------------------------------------------------------------
__global__ void transpose_kernel(const float* __restrict__ in,
                                 float* __restrict__ out,
                                 int rows, int cols) {
    __shared__ float tile[32][33];
    int bx = blockIdx.x * 32;
    int by = blockIdx.y * 32;
    size_t plane = (size_t)rows * cols;
    const float* inb = in + (size_t)blockIdx.z * plane;
    float* outb      = out + (size_t)blockIdx.z * plane;
    int tx = threadIdx.x, ty = threadIdx.y;
    #pragma unroll
    for (int i = 0; i < 32; i += 8)
        tile[ty + i][tx] = inb[(size_t)(by + ty + i) * cols + bx + tx];
    __syncthreads();
    #pragma unroll
    for (int i = 0; i < 32; i += 8)
        outb[(size_t)(bx + ty + i) * rows + by + tx] = tile[tx][ty + i];
}

// ---------------------------------------------------------------------------
// RMS norm over DIMM=384: one block (128 threads) per token
// ---------------------------------------------------------------------------
__global__ void rms_kernel(const float* __restrict__ in,
                           const float* __restrict__ scale,
                           float* __restrict__ out) {
    int tok = blockIdx.x;
    int tid = threadIdx.x;
    const float* row = in + (size_t)tok * DIMM;
    float v0 = row[tid], v1 = row[tid + 128], v2 = row[tid + 256];
    float s = v0*v0 + v1*v1 + v2*v2;
    #pragma unroll
    for (int off = 16; off > 0; off >>= 1)
        s += __shfl_down_sync(0xffffffffu, s, off);
    __shared__ float red[4];
    if ((tid & 31) == 0) red[tid >> 5] = s;
    __syncthreads();
    if (tid == 0) {
        float t = red[0] + red[1] + red[2] + red[3];
        red[0] = rsqrtf(t * (1.0f / DIMM) + 1e-6f);
    }
    __syncthreads();
    float rinv = red[0];
    float* orow = out + (size_t)tok * DIMM;
    orow[tid]       = v0 * rinv * scale[tid];
    orow[tid + 128] = v1 * rinv * scale[tid + 128];
    orow[tid + 256] = v2 * rinv * scale[tid + 256];
}

// ---------------------------------------------------------------------------
// QK rms-norm + RoPE (in-place on g_qkv). One block (384 threads) per token.
// ---------------------------------------------------------------------------
__global__ void qkrope_kernel(float* __restrict__ qkv,
                              const float* __restrict__ nq,
                              const float* __restrict__ nk,
                              const float* __restrict__ cosT,
                              const float* __restrict__ sinT) {
    int tok = blockIdx.x;
    int tid = threadIdx.x;
    size_t base = (size_t)tok * QKVN;
    float qv = qkv[base + tid];
    float kv = qkv[base + 384 + tid];
    float s2q = qv * qv, s2k = kv * kv;
    #pragma unroll
    for (int off = 16; off > 0; off >>= 1) {
        s2q += __shfl_down_sync(0xffffffffu, s2q, off);
        s2k += __shfl_down_sync(0xffffffffu, s2k, off);
    }
    __shared__ float rq[12], rk[12];
    __shared__ float sq[384], sk[384];
    int wid = tid >> 5;
    if ((tid & 31) == 0) { rq[wid] = s2q; rk[wid] = s2k; }
    __syncthreads();
    if (tid == 0) {
        float a = 0.f, b = 0.f;
        #pragma unroll
        for (int w = 0; w < 12; w++) { a += rq[w]; b += rk[w]; }
        rq[0] = rsqrtf(a * (1.0f / DIMM) + 1e-6f);
        rk[0] = rsqrtf(b * (1.0f / DIMM) + 1e-6f);
    }
    __syncthreads();
    float rinvq = rq[0], rinvk = rk[0];
    sq[tid] = qv * rinvq * nq[tid];
    sk[tid] = kv * rinvk * nk[tid];
    __syncthreads();
    int l = tok & (LL - 1);
    if (tid < 192) {
        int p = tid, hh = p >> 4, j = p & 15;
        int i0 = hh * HDIM + 2 * j;
        float c = cosT[l * 16 + j], s = sinT[l * 16 + j];
        float x0 = sq[i0], x1 = sq[i0 + 1];
        qkv[base + i0]     = x0 * c - x1 * s;
        qkv[base + i0 + 1] = x0 * s + x1 * c;
    } else {
        int p = tid - 192, hh = p >> 4, j = p & 15;
        int i0 = hh * HDIM + 2 * j;
        float c = cosT[l * 16 + j], s = sinT[l * 16 + j];
        float x0 = sk[i0], x1 = sk[i0 + 1];
        qkv[base + 384 + i0]     = x0 * c - x1 * s;
        qkv[base + 384 + i0 + 1] = x0 * s + x1 * c;
    }
}

// ---------------------------------------------------------------------------
// Attention. One CTA per (group, head); blockDim = S (sequence length).
// ---------------------------------------------------------------------------
template <int VAR>
__device__ __forceinline__ int tok_of(int g, int s) {
    if (VAR == 0) { int b = g >> 7, t = g & 127; return b * LL + t * FRR + s; }
    if (VAR == 1) { int b = g >> 6, fr = g & 63; return b * LL + s * FRR + fr; }
    int b = g >> 8, r = g & 255;
    int t1 = r >> 3, f1 = r & 7;
    int t2 = s >> 3, f2 = s & 7;
    return b * LL + (t1 * 4 + t2) * FRR + f1 * 8 + f2;
}

template <int VAR, int S, bool ACC>
__global__ void attn_kernel(const float* __restrict__ qkv,
                            float* __restrict__ ysum) {
    __shared__ float Ks[S][HDIM];
    __shared__ float Vs[S][HDIM];
    int g = blockIdx.x, h = blockIdx.y, tid = threadIdx.x;

    for (int idx = tid; idx < S * HDIM; idx += S) {
        int r = idx >> 5, d = idx & 31;
        size_t base = (size_t)tok_of<VAR>(g, r) * QKVN + h * HDIM;
        Ks[r][d] = qkv[base + 384 + d];
        Vs[r][d] = qkv[base + 768 + d];
    }
    size_t qbase = (size_t)tok_of<VAR>(g, tid) * QKVN + h * HDIM;
    float q[HDIM];
    #pragma unroll
    for (int d4 = 0; d4 < 8; d4++) {
        float4 v = *(const float4*)(qkv + qbase + d4 * 4);
        q[d4*4+0] = v.x; q[d4*4+1] = v.y; q[d4*4+2] = v.z; q[d4*4+3] = v.w;
    }
    __syncthreads();

    const float rscale = 0.17677669529663687f;
    float m = -1e30f, lsum = 0.f;
    float acc[HDIM];
    #pragma unroll
    for (int d = 0; d < HDIM; d++) acc[d] = 0.f;

    for (int j = 0; j < S; j++) {
        float s = 0.f;
        #pragma unroll
        for (int d = 0; d < HDIM; d++) s += q[d] * Ks[j][d];
        s *= rscale;
        float mn = fmaxf(m, s);
        float corr = __expf(m - mn);
        float p = __expf(s - mn);
        lsum = lsum * corr + p;
        #pragma unroll
        for (int d = 0; d < HDIM; d++) acc[d] = acc[d] * corr + p * Vs[j][d];
        m = mn;
    }
    float inv = 1.f / lsum;
    size_t obase = (size_t)tok_of<VAR>(g, tid) * DIMM + h * HDIM;
    #pragma unroll
    for (int d = 0; d < HDIM; d++) {
        if (ACC) ysum[obase + d] += acc[d] * inv;
        else     ysum[obase + d]  = acc[d] * inv;
    }
}

// ---------------------------------------------------------------------------
// TF32 tensor-core GEMM: C(M,N) = epi(A(M,K) @ B(K,N) + bias)
// 128x128x16 CTA tile, 256 threads (8 warps, 4m x 2n), warp tile 32x64.
// mma.sync.aligned.m16n8k8 tf32, cp.async double-buffered smem.
// EPI 0: store; EPI 1: gelu store; EPI 2: C += v.
// Requires M%128==0, N%128==0, K%16==0 (true for all call sites).
// ---------------------------------------------------------------------------
#define GBM 128
#define GBN 128
#define GBK 16
#define ASTR 20    // (GBK+4) floats: conflict-free A frag reads
#define BSTR 136   // (GBN+8) floats: conflict-free B frag reads

__device__ __forceinline__ float gelu_tanh(float x) {
    float c = 0.7978845608028654f;
    float t = tanhf(c * (x + 0.044715f * x * x * x));
    return 0.5f * x * (1.0f + t);
}

__device__ __forceinline__ unsigned f2tf32(float x) {
    unsigned y;
    asm volatile("cvt.rna.tf32.f32 %0, %1;\n" : "=r"(y) : "f"(x));
    return y;
}

__device__ __forceinline__ void cp16(void* smem, const void* gmem) {
    unsigned s = (unsigned)__cvta_generic_to_shared(smem);
    asm volatile("cp.async.cg.shared.global [%0], [%1], 16;\n" :: "r"(s), "l"(gmem));
}
#define CP_COMMIT() asm volatile("cp.async.commit_group;\n" ::: "memory")
#define CP_WAIT(n)  asm volatile("cp.async.wait_group %0;\n" :: "n"(n) : "memory")

__device__ __forceinline__ void mma_tf32(float* c, const unsigned* a, const unsigned* b) {
    asm volatile(
        "mma.sync.aligned.m16n8k8.row.col.f32.tf32.tf32.f32 "
        "{%0,%1,%2,%3}, {%4,%5,%6,%7}, {%8,%9}, {%0,%1,%2,%3};\n"
        : "+f"(c[0]), "+f"(c[1]), "+f"(c[2]), "+f"(c[3])
        : "r"(a[0]), "r"(a[1]), "r"(a[2]), "r"(a[3]), "r"(b[0]), "r"(b[1]));
}

template <int EPI>
__global__ __launch_bounds__(256)
void mma_gemm(const float* __restrict__ A, const float* __restrict__ B,
              const float* __restrict__ bias, float* __restrict__ C,
              int M, int N, int K) {
    __shared__ float As[2][GBM][ASTR];   // [m][k], stride 20
    __shared__ float Bs[2][GBK][BSTR];   // [k][n], stride 136

    int tid  = threadIdx.x;
    int n0   = blockIdx.x * GBN, m0 = blockIdx.y * GBM;
    int warp = tid >> 5, lane = tid & 31;
    int gid  = lane >> 2, tid4 = lane & 3;
    int wm   = (warp & 3) * 32;      // warp m offset in tile
    int wn   = (warp >> 2) * 64;     // warp n offset in tile

    const float* Abase = A + (size_t)m0 * K;
    const float* Bbase = B + n0;

    float c[2][8][4];
    #pragma unroll
    for (int mt = 0; mt < 2; mt++)
        #pragma unroll
        for (int nt = 0; nt < 8; nt++)
            #pragma unroll
            for (int r = 0; r < 4; r++) c[mt][nt][r] = 0.f;

    // A tile: 128 rows x 16 cols = 512 x 16B chunks; this thread: tid, tid+256
    // B tile: 16 rows x 128 cols = 512 x 16B chunks
    auto load_tiles = [&](int buf, int k0) {
        #pragma unroll
        for (int i = 0; i < 2; i++) {
            int ch = tid + i * 256;
            int am = ch >> 2, akc = ch & 3;
            cp16(&As[buf][am][akc * 4], Abase + (size_t)am * K + k0 + akc * 4);
            int bk = ch >> 5, bnc = ch & 31;
            cp16(&Bs[buf][bk][bnc * 4], Bbase + (size_t)(k0 + bk) * N + bnc * 4);
        }
    };

    int kTiles = K / GBK;
    load_tiles(0, 0);
    CP_COMMIT();

    for (int kt = 0; kt < kTiles; kt++) {
        int buf = kt & 1;
        if (kt + 1 < kTiles) {
            load_tiles(buf ^ 1, (kt + 1) * GBK);
            CP_COMMIT();
            CP_WAIT(1);
        } else {
            CP_WAIT(0);
        }
        __syncthreads();

        #pragma unroll
        for (int ks = 0; ks < GBK; ks += 8) {
            unsigned af[2][4], bf[8][2];
            #pragma unroll
            for (int mt = 0; mt < 2; mt++) {
                int r = wm + mt * 16 + gid;
                af[mt][0] = f2tf32(As[buf][r][ks + tid4]);
                af[mt][1] = f2tf32(As[buf][r + 8][ks + tid4]);
                af[mt][2] = f2tf32(As[buf][r][ks + tid4 + 4]);
                af[mt][3] = f2tf32(As[buf][r + 8][ks + tid4 + 4]);
            }
            #pragma unroll
            for (int nt = 0; nt < 8; nt++) {
                int col = wn + nt * 8 + gid;
                bf[nt][0] = f2tf32(Bs[buf][ks + tid4][col]);
                bf[nt][1] = f2tf32(Bs[buf][ks + tid4 + 4][col]);
            }
            #pragma unroll
            for (int mt = 0; mt < 2; mt++)
                #pragma unroll
                for (int nt = 0; nt < 8; nt++)
                    mma_tf32(c[mt][nt], af[mt], bf[nt]);
        }
        __syncthreads();
    }

    // epilogue: c[mt][nt] covers rows {r0, r0+8}, cols {cc, cc+1}
    #pragma unroll
    for (int mt = 0; mt < 2; mt++) {
        int r0 = m0 + wm + mt * 16 + gid;
        int r1 = r0 + 8;
        #pragma unroll
        for (int nt = 0; nt < 8; nt++) {
            int cc = n0 + wn + nt * 8 + 2 * tid4;
            float b0 = bias[cc], b1 = bias[cc + 1];
            float v00 = c[mt][nt][0] + b0, v01 = c[mt][nt][1] + b1;
            float v10 = c[mt][nt][2] + b0, v11 = c[mt][nt][3] + b1;
            float* p0 = C + (size_t)r0 * N + cc;
            float* p1 = C + (size_t)r1 * N + cc;
            if (EPI == 0) {
                *(float2*)p0 = make_float2(v00, v01);
                *(float2*)p1 = make_float2(v10, v11);
            } else if (EPI == 1) {
                *(float2*)p0 = make_float2(gelu_tanh(v00), gelu_tanh(v01));
                *(float2*)p1 = make_float2(gelu_tanh(v10), gelu_tanh(v11));
            } else {
                float2 o0 = *(float2*)p0, o1 = *(float2*)p1;
                *(float2*)p0 = make_float2(o0.x + v00, o0.y + v01);
                *(float2*)p1 = make_float2(o1.x + v10, o1.y + v11);
            }
        }
    }
}

// ---------------------------------------------------------------------------
// kernel_launch
// ---------------------------------------------------------------------------
extern "C" void kernel_launch(void* const* d_in, const int* in_sizes, int n_in,
                              void* d_out, int out_size) {
    const float* x      = (const float*)d_in[0];
    const float* cosT   = (const float*)d_in[1];
    const float* sinT   = (const float*)d_in[2];
    const float* qkv_w  = (const float*)d_in[3];
    const float* qkv_b  = (const float*)d_in[4];
    const float* nq_s   = (const float*)d_in[5];
    const float* nk_s   = (const float*)d_in[6];
    const float* proj_w = (const float*)d_in[7];
    const float* proj_b = (const float*)d_in[8];
    const float* n1_s   = (const float*)d_in[9];
    const float* n2_s   = (const float*)d_in[10];
    const float* w1     = (const float*)d_in[11];
    const float* b1     = (const float*)d_in[12];
    const float* w2     = (const float*)d_in[13];
    const float* b2     = (const float*)d_in[14];
    float* out = (float*)d_out;

    float *xs, *xn, *qkv, *ysum, *h, *h1;
    cudaGetSymbolAddress((void**)&xs,   g_xs);
    cudaGetSymbolAddress((void**)&xn,   g_xn);
    cudaGetSymbolAddress((void**)&qkv,  g_qkv);
    cudaGetSymbolAddress((void**)&ysum, g_ysum);
    cudaGetSymbolAddress((void**)&h,    g_h);
    cudaGetSymbolAddress((void**)&h1,   g_h1);

    dim3 tb(32, 8);

    // 1) x (B, DIM, L) -> xs (B, L, DIM)
    transpose_kernel<<<dim3(LL / 32, DIMM / 32, BB), tb>>>(x, xs, DIMM, LL);

    // 2) xn = rms(xs, n1_s)
    rms_kernel<<<NTOK, 128>>>(xs, n1_s, xn);

    // 3) qkv = xn @ qkv_w + qkv_b   (tensor cores)
    mma_gemm<0><<<dim3(QKVN / GBN, NTOK / GBM), 256>>>(xn, qkv_w, qkv_b,
                                                       qkv, NTOK, QKVN, DIMM);

    // 4) q/k rmsnorm + rope (in-place)
    qkrope_kernel<<<NTOK, 384>>>(qkv, nq_s, nk_s, cosT, sinT);

    // 5-7) three attentions, summed into ysum
    attn_kernel<0, 64,  false><<<dim3(BB * TT,  NHEAD), 64 >>>(qkv, ysum);
    attn_kernel<1, 128, true ><<<dim3(BB * FRR, NHEAD), 128>>>(qkv, ysum);
    attn_kernel<2, 32,  true ><<<dim3(BB * 256, NHEAD), 32 >>>(qkv, ysum);

    // 8) xs += ysum @ proj_w + proj_b
    mma_gemm<2><<<dim3(DIMM / GBN, NTOK / GBM), 256>>>(ysum, proj_w, proj_b,
                                                       xs, NTOK, DIMM, DIMM);

    // 9) h = rms(xs, n2_s)
    rms_kernel<<<NTOK, 128>>>(xs, n2_s, h);

    // 10) h1 = gelu(h @ w1 + b1)
    mma_gemm<1><<<dim3(FFN / GBN, NTOK / GBM), 256>>>(h, w1, b1,
                                                      h1, NTOK, FFN, DIMM);

    // 11) xs += h1 @ w2 + b2
    mma_gemm<2><<<dim3(DIMM / GBN, NTOK / GBM), 256>>>(h1, w2, b2,
                                                       xs, NTOK, DIMM, FFN);

    // 12) xs (B, L, DIM) -> out (B, DIM, L)
    transpose_kernel<<<dim3(DIMM / 32, LL / 32, BB), tb>>>(xs, out, LL, DIMM);
}

// round 5
// speedup vs baseline: 2.2136x; 1.0681x over previous
#include <cuda_runtime.h>
#include <cuda_bf16.h>
#include <math.h>

#define BB    4
#define TT    128
#define FRR   64
#define LL    8192
#define DIMM  384
#define NHEAD 12
#define HDIM  32
#define NTOK  (BB*LL)
#define QKVN  (3*DIMM)
#define FFN   (4*DIMM)

// ---------------------------------------------------------------------------
// Scratch
// ---------------------------------------------------------------------------
__device__ float g_xs  [(size_t)NTOK * DIMM];
__device__ float g_xn  [(size_t)NTOK * DIMM];
__device__ float g_qkv [(size_t)NTOK * QKVN];
__device__ float g_ysum[(size_t)NTOK * DIMM];
__device__ float g_h   [(size_t)NTOK * DIMM];
__device__ float g_h1  [(size_t)NTOK * FFN];
__device__ float g_wqkv[DIMM * QKVN];
__device__ float g_wproj[DIMM * DIMM];
__device__ float g_w1  [DIMM * FFN];
__device__ float g_w2  [FFN * DIMM];

__device__ __forceinline__ float tf32r(float x) {
    unsigned y;
    asm volatile("cvt.rna.tf32.f32 %0, %1;\n" : "=r"(y) : "f"(x));
    return __uint_as_float(y);
}

// ---------------------------------------------------------------------------
// Round weights to tf32 once
// ---------------------------------------------------------------------------
__global__ void round_w_kernel(const float* __restrict__ in,
                               float* __restrict__ out, int n) {
    int i = blockIdx.x * blockDim.x + threadIdx.x;
    if (i < n) out[i] = tf32r(in[i]);
}

// ---------------------------------------------------------------------------
// Fused input transpose + rms1.
// x (B, 384, L) -> xs (B*L, 384) raw, xn = tf32(rms(xs)*n1).
// CTA: 16 tokens. grid (L/16, B), 256 threads.
// ---------------------------------------------------------------------------
__global__ __launch_bounds__(256)
void fuse_in_kernel(const float* __restrict__ x,
                    const float* __restrict__ n1,
                    float* __restrict__ xs, float* __restrict__ xn) {
    __shared__ float tile[DIMM][17];
    __shared__ float rinv[16];
    int tid = threadIdx.x;
    int l0 = blockIdx.x * 16;
    int b  = blockIdx.y;
    const float* xb = x + (size_t)b * DIMM * LL + l0;

    #pragma unroll
    for (int it = 0; it < 24; it++) {               // 384*16/256
        int idx = tid + it * 256;
        int d = idx >> 4, c = idx & 15;
        tile[d][c] = xb[(size_t)d * LL + c];
    }
    __syncthreads();

    // rms: 16 threads per token, 24 elems each
    int tok = tid >> 4, j = tid & 15;
    float s = 0.f;
    #pragma unroll
    for (int k = 0; k < 24; k++) {
        float v = tile[j + 16 * k][tok];
        s += v * v;
    }
    #pragma unroll
    for (int m = 8; m >= 1; m >>= 1)
        s += __shfl_xor_sync(0xffffffffu, s, m);
    if (j == 0) rinv[tok] = rsqrtf(s * (1.0f / DIMM) + 1e-6f);
    __syncthreads();

    size_t gbase = ((size_t)b * LL + l0) * DIMM;
    #pragma unroll
    for (int it = 0; it < 24; it++) {
        int idx = tid + it * 256;
        int t2 = idx / DIMM, d = idx - t2 * DIMM;
        float raw = tile[d][t2];
        xs[gbase + (size_t)t2 * DIMM + d] = raw;
        xn[gbase + (size_t)t2 * DIMM + d] = tf32r(raw * rinv[t2] * n1[d]);
    }
}

// ---------------------------------------------------------------------------
// Output transpose: xs (B, L, 384) -> out (B, 384, L)
// ---------------------------------------------------------------------------
__global__ void transpose_kernel(const float* __restrict__ in,
                                 float* __restrict__ out,
                                 int rows, int cols) {
    __shared__ float tile[32][33];
    int bx = blockIdx.x * 32;
    int by = blockIdx.y * 32;
    size_t plane = (size_t)rows * cols;
    const float* inb = in + (size_t)blockIdx.z * plane;
    float* outb      = out + (size_t)blockIdx.z * plane;
    int tx = threadIdx.x, ty = threadIdx.y;
    #pragma unroll
    for (int i = 0; i < 32; i += 8)
        tile[ty + i][tx] = inb[(size_t)(by + ty + i) * cols + bx + tx];
    __syncthreads();
    #pragma unroll
    for (int i = 0; i < 32; i += 8)
        outb[(size_t)(bx + ty + i) * rows + by + tx] = tile[tx][ty + i];
}

// ---------------------------------------------------------------------------
// rms2: h = tf32(rms(xs)*n2). One block (128 threads) per token.
// ---------------------------------------------------------------------------
__global__ void rms_kernel(const float* __restrict__ in,
                           const float* __restrict__ scale,
                           float* __restrict__ out) {
    int tok = blockIdx.x;
    int tid = threadIdx.x;
    const float* row = in + (size_t)tok * DIMM;
    float v0 = row[tid], v1 = row[tid + 128], v2 = row[tid + 256];
    float s = v0*v0 + v1*v1 + v2*v2;
    #pragma unroll
    for (int off = 16; off > 0; off >>= 1)
        s += __shfl_down_sync(0xffffffffu, s, off);
    __shared__ float red[4];
    if ((tid & 31) == 0) red[tid >> 5] = s;
    __syncthreads();
    if (tid == 0) {
        float t = red[0] + red[1] + red[2] + red[3];
        red[0] = rsqrtf(t * (1.0f / DIMM) + 1e-6f);
    }
    __syncthreads();
    float rinv = red[0];
    float* orow = out + (size_t)tok * DIMM;
    orow[tid]       = tf32r(v0 * rinv * scale[tid]);
    orow[tid + 128] = tf32r(v1 * rinv * scale[tid + 128]);
    orow[tid + 256] = tf32r(v2 * rinv * scale[tid + 256]);
}

// ---------------------------------------------------------------------------
// QK rms-norm + RoPE, warp-per-token, vectorized, no block sync.
// block 128 = 4 warps = 4 tokens. grid NTOK/4.
// ---------------------------------------------------------------------------
__global__ __launch_bounds__(128)
void qkrope_kernel(float* __restrict__ qkv,
                   const float* __restrict__ nq,
                   const float* __restrict__ nk,
                   const float* __restrict__ cosT,
                   const float* __restrict__ sinT) {
    int tid = threadIdx.x;
    int lane = tid & 31;
    int tok = blockIdx.x * 4 + (tid >> 5);
    size_t base = (size_t)tok * QKVN;
    float* qp = qkv + base;
    float* kp = qkv + base + DIMM;

    float4 qv[3], kv[3];
    float ssq = 0.f, ssk = 0.f;
    #pragma unroll
    for (int i = 0; i < 3; i++) {
        int e0 = i * 128 + lane * 4;
        qv[i] = *(const float4*)(qp + e0);
        kv[i] = *(const float4*)(kp + e0);
        ssq += qv[i].x*qv[i].x + qv[i].y*qv[i].y + qv[i].z*qv[i].z + qv[i].w*qv[i].w;
        ssk += kv[i].x*kv[i].x + kv[i].y*kv[i].y + kv[i].z*kv[i].z + kv[i].w*kv[i].w;
    }
    #pragma unroll
    for (int m = 16; m >= 1; m >>= 1) {
        ssq += __shfl_xor_sync(0xffffffffu, ssq, m);
        ssk += __shfl_xor_sync(0xffffffffu, ssk, m);
    }
    float rq = rsqrtf(ssq * (1.0f / DIMM) + 1e-6f);
    float rk = rsqrtf(ssk * (1.0f / DIMM) + 1e-6f);

    int l = tok & (LL - 1);
    int j2 = 2 * (lane & 7);
    float c0 = cosT[l * 16 + j2],     s0 = sinT[l * 16 + j2];
    float c1 = cosT[l * 16 + j2 + 1], s1 = sinT[l * 16 + j2 + 1];

    #pragma unroll
    for (int i = 0; i < 3; i++) {
        int e0 = i * 128 + lane * 4;
        float4 nqv = *(const float4*)(nq + e0);
        float4 nkv = *(const float4*)(nk + e0);
        float a0 = qv[i].x * rq * nqv.x, a1 = qv[i].y * rq * nqv.y;
        float a2 = qv[i].z * rq * nqv.z, a3 = qv[i].w * rq * nqv.w;
        float4 o;
        o.x = a0 * c0 - a1 * s0;  o.y = a0 * s0 + a1 * c0;
        o.z = a2 * c1 - a3 * s1;  o.w = a2 * s1 + a3 * c1;
        *(float4*)(qp + e0) = o;
        float b0 = kv[i].x * rk * nkv.x, b1 = kv[i].y * rk * nkv.y;
        float b2 = kv[i].z * rk * nkv.z, b3 = kv[i].w * rk * nkv.w;
        float4 p;
        p.x = b0 * c0 - b1 * s0;  p.y = b0 * s0 + b1 * c0;
        p.z = b2 * c1 - b3 * s1;  p.w = b2 * s1 + b3 * c1;
        *(float4*)(kp + e0) = p;
    }
}

// ---------------------------------------------------------------------------
// Attention: single-pass softmax (scores bounded: |s|<=~5.7, exp safe).
// MODE 0: write; MODE 1: +=; MODE 2: += and round total to tf32.
// ---------------------------------------------------------------------------
template <int VAR>
__device__ __forceinline__ int tok_of(int g, int s) {
    if (VAR == 0) { int b = g >> 7, t = g & 127; return b * LL + t * FRR + s; }
    if (VAR == 1) { int b = g >> 6, fr = g & 63; return b * LL + s * FRR + fr; }
    int b = g >> 8, r = g & 255;
    int t1 = r >> 3, f1 = r & 7;
    int t2 = s >> 3, f2 = s & 7;
    return b * LL + (t1 * 4 + t2) * FRR + f1 * 8 + f2;
}

template <int VAR, int S, int MODE>
__global__ void attn_kernel(const float* __restrict__ qkv,
                            float* __restrict__ ysum) {
    __shared__ float Ks[S][HDIM];
    __shared__ float Vs[S][HDIM];
    int g = blockIdx.x, h = blockIdx.y, tid = threadIdx.x;

    for (int idx = tid; idx < S * HDIM; idx += S) {
        int r = idx >> 5, d = idx & 31;
        size_t base = (size_t)tok_of<VAR>(g, r) * QKVN + h * HDIM;
        Ks[r][d] = qkv[base + 384 + d];
        Vs[r][d] = qkv[base + 768 + d];
    }
    size_t qbase = (size_t)tok_of<VAR>(g, tid) * QKVN + h * HDIM;
    float q[HDIM];
    #pragma unroll
    for (int d4 = 0; d4 < 8; d4++) {
        float4 v = *(const float4*)(qkv + qbase + d4 * 4);
        q[d4*4+0] = v.x; q[d4*4+1] = v.y; q[d4*4+2] = v.z; q[d4*4+3] = v.w;
    }
    __syncthreads();

    const float rscale = 0.17677669529663687f;
    float lsum = 0.f;
    float acc[HDIM];
    #pragma unroll
    for (int d = 0; d < HDIM; d++) acc[d] = 0.f;

    for (int j = 0; j < S; j++) {
        float s = 0.f;
        #pragma unroll
        for (int d = 0; d < HDIM; d++) s += q[d] * Ks[j][d];
        float p = __expf(s * rscale);
        lsum += p;
        #pragma unroll
        for (int d = 0; d < HDIM; d++) acc[d] += p * Vs[j][d];
    }
    float inv = 1.f / lsum;
    size_t obase = (size_t)tok_of<VAR>(g, tid) * DIMM + h * HDIM;
    #pragma unroll
    for (int d = 0; d < HDIM; d++) {
        if (MODE == 0)      ysum[obase + d] = acc[d] * inv;
        else if (MODE == 1) ysum[obase + d] += acc[d] * inv;
        else                ysum[obase + d] = tf32r(ysum[obase + d] + acc[d] * inv);
    }
}

// ---------------------------------------------------------------------------
// TF32 tensor-core GEMM (inputs pre-rounded to tf32 by producers).
// 128x128x16 tile, 256 threads, warp tile 32x64, double-buffered cp.async.
// EPI 0: store; EPI 1: tf32(gelu) store; EPI 2: C += v.
// ---------------------------------------------------------------------------
#define GBM 128
#define GBN 128
#define GBK 16
#define ASTR 20
#define BSTR 136

__device__ __forceinline__ float gelu_tanh(float x) {
    float c = 0.7978845608028654f;
    float t = tanhf(c * (x + 0.044715f * x * x * x));
    return 0.5f * x * (1.0f + t);
}

__device__ __forceinline__ void cp16(void* smem, const void* gmem) {
    unsigned s = (unsigned)__cvta_generic_to_shared(smem);
    asm volatile("cp.async.cg.shared.global [%0], [%1], 16;\n" :: "r"(s), "l"(gmem));
}
#define CP_COMMIT() asm volatile("cp.async.commit_group;\n" ::: "memory")
#define CP_WAIT(n)  asm volatile("cp.async.wait_group %0;\n" :: "n"(n) : "memory")

__device__ __forceinline__ void mma_tf32(float* c, const unsigned* a, const unsigned* b) {
    asm volatile(
        "mma.sync.aligned.m16n8k8.row.col.f32.tf32.tf32.f32 "
        "{%0,%1,%2,%3}, {%4,%5,%6,%7}, {%8,%9}, {%0,%1,%2,%3};\n"
        : "+f"(c[0]), "+f"(c[1]), "+f"(c[2]), "+f"(c[3])
        : "r"(a[0]), "r"(a[1]), "r"(a[2]), "r"(a[3]), "r"(b[0]), "r"(b[1]));
}

template <int EPI>
__global__ __launch_bounds__(256, 2)
void mma_gemm(const float* __restrict__ A, const float* __restrict__ B,
              const float* __restrict__ bias, float* __restrict__ C,
              int M, int N, int K) {
    __shared__ float As[2][GBM][ASTR];
    __shared__ float Bs[2][GBK][BSTR];

    int tid  = threadIdx.x;
    int n0   = blockIdx.x * GBN, m0 = blockIdx.y * GBM;
    int warp = tid >> 5, lane = tid & 31;
    int gid  = lane >> 2, tid4 = lane & 3;
    int wm   = (warp & 3) * 32;
    int wn   = (warp >> 2) * 64;

    const float* Abase = A + (size_t)m0 * K;
    const float* Bbase = B + n0;

    float c[2][8][4];
    #pragma unroll
    for (int mt = 0; mt < 2; mt++)
        #pragma unroll
        for (int nt = 0; nt < 8; nt++)
            #pragma unroll
            for (int r = 0; r < 4; r++) c[mt][nt][r] = 0.f;

    auto load_tiles = [&](int buf, int k0) {
        #pragma unroll
        for (int i = 0; i < 2; i++) {
            int ch = tid + i * 256;
            int am = ch >> 2, akc = ch & 3;
            cp16(&As[buf][am][akc * 4], Abase + (size_t)am * K + k0 + akc * 4);
            int bk = ch >> 5, bnc = ch & 31;
            cp16(&Bs[buf][bk][bnc * 4], Bbase + (size_t)(k0 + bk) * N + bnc * 4);
        }
    };

    int kTiles = K / GBK;
    load_tiles(0, 0);
    CP_COMMIT();

    for (int kt = 0; kt < kTiles; kt++) {
        int buf = kt & 1;
        if (kt + 1 < kTiles) {
            load_tiles(buf ^ 1, (kt + 1) * GBK);
            CP_COMMIT();
            CP_WAIT(1);
        } else {
            CP_WAIT(0);
        }
        __syncthreads();

        #pragma unroll
        for (int ks = 0; ks < GBK; ks += 8) {
            unsigned af[2][4], bf[8][2];
            #pragma unroll
            for (int mt = 0; mt < 2; mt++) {
                int r = wm + mt * 16 + gid;
                af[mt][0] = __float_as_uint(As[buf][r][ks + tid4]);
                af[mt][1] = __float_as_uint(As[buf][r + 8][ks + tid4]);
                af[mt][2] = __float_as_uint(As[buf][r][ks + tid4 + 4]);
                af[mt][3] = __float_as_uint(As[buf][r + 8][ks + tid4 + 4]);
            }
            #pragma unroll
            for (int nt = 0; nt < 8; nt++) {
                int col = wn + nt * 8 + gid;
                bf[nt][0] = __float_as_uint(Bs[buf][ks + tid4][col]);
                bf[nt][1] = __float_as_uint(Bs[buf][ks + tid4 + 4][col]);
            }
            #pragma unroll
            for (int mt = 0; mt < 2; mt++)
                #pragma unroll
                for (int nt = 0; nt < 8; nt++)
                    mma_tf32(c[mt][nt], af[mt], bf[nt]);
        }
        __syncthreads();
    }

    #pragma unroll
    for (int mt = 0; mt < 2; mt++) {
        int r0 = m0 + wm + mt * 16 + gid;
        int r1 = r0 + 8;
        #pragma unroll
        for (int nt = 0; nt < 8; nt++) {
            int cc = n0 + wn + nt * 8 + 2 * tid4;
            float b0 = bias[cc], b1 = bias[cc + 1];
            float v00 = c[mt][nt][0] + b0, v01 = c[mt][nt][1] + b1;
            float v10 = c[mt][nt][2] + b0, v11 = c[mt][nt][3] + b1;
            float* p0 = C + (size_t)r0 * N + cc;
            float* p1 = C + (size_t)r1 * N + cc;
            if (EPI == 0) {
                *(float2*)p0 = make_float2(v00, v01);
                *(float2*)p1 = make_float2(v10, v11);
            } else if (EPI == 1) {
                *(float2*)p0 = make_float2(tf32r(gelu_tanh(v00)), tf32r(gelu_tanh(v01)));
                *(float2*)p1 = make_float2(tf32r(gelu_tanh(v10)), tf32r(gelu_tanh(v11)));
            } else {
                float2 o0 = *(float2*)p0, o1 = *(float2*)p1;
                *(float2*)p0 = make_float2(o0.x + v00, o0.y + v01);
                *(float2*)p1 = make_float2(o1.x + v10, o1.y + v11);
            }
        }
    }
}

// ---------------------------------------------------------------------------
// kernel_launch
// ---------------------------------------------------------------------------
extern "C" void kernel_launch(void* const* d_in, const int* in_sizes, int n_in,
                              void* d_out, int out_size) {
    const float* x      = (const float*)d_in[0];
    const float* cosT   = (const float*)d_in[1];
    const float* sinT   = (const float*)d_in[2];
    const float* qkv_w  = (const float*)d_in[3];
    const float* qkv_b  = (const float*)d_in[4];
    const float* nq_s   = (const float*)d_in[5];
    const float* nk_s   = (const float*)d_in[6];
    const float* proj_w = (const float*)d_in[7];
    const float* proj_b = (const float*)d_in[8];
    const float* n1_s   = (const float*)d_in[9];
    const float* n2_s   = (const float*)d_in[10];
    const float* w1     = (const float*)d_in[11];
    const float* b1     = (const float*)d_in[12];
    const float* w2     = (const float*)d_in[13];
    const float* b2     = (const float*)d_in[14];
    float* out = (float*)d_out;

    float *xs, *xn, *qkv, *ysum, *h, *h1, *wq, *wp, *ww1, *ww2;
    cudaGetSymbolAddress((void**)&xs,   g_xs);
    cudaGetSymbolAddress((void**)&xn,   g_xn);
    cudaGetSymbolAddress((void**)&qkv,  g_qkv);
    cudaGetSymbolAddress((void**)&ysum, g_ysum);
    cudaGetSymbolAddress((void**)&h,    g_h);
    cudaGetSymbolAddress((void**)&h1,   g_h1);
    cudaGetSymbolAddress((void**)&wq,   g_wqkv);
    cudaGetSymbolAddress((void**)&wp,   g_wproj);
    cudaGetSymbolAddress((void**)&ww1,  g_w1);
    cudaGetSymbolAddress((void**)&ww2,  g_w2);

    // 1-4) pre-round weights to tf32 (launches 1-4)
    round_w_kernel<<<(DIMM*QKVN + 255)/256, 256>>>(qkv_w, wq, DIMM*QKVN);
    round_w_kernel<<<(DIMM*DIMM + 255)/256, 256>>>(proj_w, wp, DIMM*DIMM);
    round_w_kernel<<<(DIMM*FFN  + 255)/256, 256>>>(w1, ww1, DIMM*FFN);
    round_w_kernel<<<(FFN*DIMM  + 255)/256, 256>>>(w2, ww2, FFN*DIMM);

    // 5) fused transpose + rms1 (launch 5)
    fuse_in_kernel<<<dim3(LL/16, BB), 256>>>(x, n1_s, xs, xn);

    // 6) qkv GEMM (launch 6 — ncu -s 5 -c 1 captures this one)
    mma_gemm<0><<<dim3(QKVN/GBN, NTOK/GBM), 256>>>(xn, wq, qkv_b,
                                                   qkv, NTOK, QKVN, DIMM);

    // 7) q/k rmsnorm + rope
    qkrope_kernel<<<NTOK/4, 128>>>(qkv, nq_s, nk_s, cosT, sinT);

    // 8-10) three attentions
    attn_kernel<0, 64,  0><<<dim3(BB * TT,  NHEAD), 64 >>>(qkv, ysum);
    attn_kernel<1, 128, 1><<<dim3(BB * FRR, NHEAD), 128>>>(qkv, ysum);
    attn_kernel<2, 32,  2><<<dim3(BB * 256, NHEAD), 32 >>>(qkv, ysum);

    // 11) xs += ysum @ proj_w + proj_b
    mma_gemm<2><<<dim3(DIMM/GBN, NTOK/GBM), 256>>>(ysum, wp, proj_b,
                                                   xs, NTOK, DIMM, DIMM);

    // 12) h = tf32(rms(xs, n2))
    rms_kernel<<<NTOK, 128>>>(xs, n2_s, h);

    // 13) h1 = tf32(gelu(h @ w1 + b1))
    mma_gemm<1><<<dim3(FFN/GBN, NTOK/GBM), 256>>>(h, ww1, b1,
                                                  h1, NTOK, FFN, DIMM);

    // 14) xs += h1 @ w2 + b2
    mma_gemm<2><<<dim3(DIMM/GBN, NTOK/GBM), 256>>>(h1, ww2, b2,
                                                   xs, NTOK, DIMM, FFN);

    // 15) xs -> out
    transpose_kernel<<<dim3(DIMM/32, LL/32, BB), dim3(32,8)>>>(xs, out, LL, DIMM);
}

// round 6
// speedup vs baseline: 2.4651x; 1.1136x over previous
#include <cuda_runtime.h>
#include <cuda_bf16.h>
#include <math.h>

#define BB    4
#define TT    128
#define FRR   64
#define LL    8192
#define DIMM  384
#define NHEAD 12
#define HDIM  32
#define NTOK  (BB*LL)
#define QKVN  (3*DIMM)
#define FFN   (4*DIMM)

typedef __nv_bfloat16  bf16;
typedef __nv_bfloat162 bf162;

// ---------------------------------------------------------------------------
// Scratch
// ---------------------------------------------------------------------------
__device__ float g_xs  [(size_t)NTOK * DIMM];   // residual (f32)
__device__ bf16  g_xnb [(size_t)NTOK * DIMM];   // rms1 out (bf16, GEMM A)
__device__ float g_qkv [(size_t)NTOK * QKVN];   // qkv (f32)
__device__ float g_ysum[(size_t)NTOK * DIMM];   // y1+y2+y3 (f32)
__device__ bf16  g_ysb [(size_t)NTOK * DIMM];   // bf16 copy for proj GEMM A
__device__ bf16  g_hb  [(size_t)NTOK * DIMM];   // rms2 out (bf16)
__device__ bf16  g_h1b [(size_t)NTOK * FFN];    // gelu out (bf16)
__device__ bf16  g_wqkv [QKVN * DIMM];          // weights transposed [N][K] bf16
__device__ bf16  g_wproj[DIMM * DIMM];
__device__ bf16  g_w1   [FFN * DIMM];
__device__ bf16  g_w2   [DIMM * FFN];

// ---------------------------------------------------------------------------
// Weight prep: w [K][N] f32 -> wt [N][K] bf16
// ---------------------------------------------------------------------------
__global__ void wprep_kernel(const float* __restrict__ w,
                             bf16* __restrict__ wt, int K, int N) {
    __shared__ float tile[32][33];
    int n0 = blockIdx.x * 32, k0 = blockIdx.y * 32;
    int tx = threadIdx.x, ty = threadIdx.y;
    #pragma unroll
    for (int i = 0; i < 32; i += 8)
        tile[ty + i][tx] = w[(size_t)(k0 + ty + i) * N + n0 + tx];
    __syncthreads();
    #pragma unroll
    for (int i = 0; i < 32; i += 8)
        wt[(size_t)(n0 + ty + i) * K + k0 + tx] =
            __float2bfloat16_rn(tile[tx][ty + i]);
}

// ---------------------------------------------------------------------------
// Fused input transpose + rms1: x (B,384,L) -> xs f32 (B*L,384), xnb bf16
// ---------------------------------------------------------------------------
__global__ __launch_bounds__(256)
void fuse_in_kernel(const float* __restrict__ x,
                    const float* __restrict__ n1,
                    float* __restrict__ xs, bf16* __restrict__ xnb) {
    __shared__ float tile[DIMM][17];
    __shared__ float rinv[16];
    int tid = threadIdx.x;
    int l0 = blockIdx.x * 16;
    int b  = blockIdx.y;
    const float* xb = x + (size_t)b * DIMM * LL + l0;

    #pragma unroll
    for (int it = 0; it < 24; it++) {
        int idx = tid + it * 256;
        int d = idx >> 4, c = idx & 15;
        tile[d][c] = xb[(size_t)d * LL + c];
    }
    __syncthreads();

    int tok = tid >> 4, j = tid & 15;
    float s = 0.f;
    #pragma unroll
    for (int k = 0; k < 24; k++) {
        float v = tile[j + 16 * k][tok];
        s += v * v;
    }
    #pragma unroll
    for (int m = 8; m >= 1; m >>= 1)
        s += __shfl_xor_sync(0xffffffffu, s, m);
    if (j == 0) rinv[tok] = rsqrtf(s * (1.0f / DIMM) + 1e-6f);
    __syncthreads();

    size_t gbase = ((size_t)b * LL + l0) * DIMM;
    #pragma unroll
    for (int it = 0; it < 24; it++) {
        int idx = tid + it * 256;
        int t2 = idx / DIMM, d = idx - t2 * DIMM;
        float raw = tile[d][t2];
        xs[gbase + (size_t)t2 * DIMM + d] = raw;
        xnb[gbase + (size_t)t2 * DIMM + d] =
            __float2bfloat16_rn(raw * rinv[t2] * n1[d]);
    }
}

// ---------------------------------------------------------------------------
// Output transpose: xs (B, L, 384) -> out (B, 384, L)
// ---------------------------------------------------------------------------
__global__ void transpose_kernel(const float* __restrict__ in,
                                 float* __restrict__ out,
                                 int rows, int cols) {
    __shared__ float tile[32][33];
    int bx = blockIdx.x * 32;
    int by = blockIdx.y * 32;
    size_t plane = (size_t)rows * cols;
    const float* inb = in + (size_t)blockIdx.z * plane;
    float* outb      = out + (size_t)blockIdx.z * plane;
    int tx = threadIdx.x, ty = threadIdx.y;
    #pragma unroll
    for (int i = 0; i < 32; i += 8)
        tile[ty + i][tx] = inb[(size_t)(by + ty + i) * cols + bx + tx];
    __syncthreads();
    #pragma unroll
    for (int i = 0; i < 32; i += 8)
        outb[(size_t)(bx + ty + i) * rows + by + tx] = tile[tx][ty + i];
}

// ---------------------------------------------------------------------------
// rms2: hb = bf16(rms(xs)*n2). One block (128 threads) per token.
// ---------------------------------------------------------------------------
__global__ void rms_kernel(const float* __restrict__ in,
                           const float* __restrict__ scale,
                           bf16* __restrict__ out) {
    int tok = blockIdx.x;
    int tid = threadIdx.x;
    const float* row = in + (size_t)tok * DIMM;
    float v0 = row[tid], v1 = row[tid + 128], v2 = row[tid + 256];
    float s = v0*v0 + v1*v1 + v2*v2;
    #pragma unroll
    for (int off = 16; off > 0; off >>= 1)
        s += __shfl_down_sync(0xffffffffu, s, off);
    __shared__ float red[4];
    if ((tid & 31) == 0) red[tid >> 5] = s;
    __syncthreads();
    if (tid == 0) {
        float t = red[0] + red[1] + red[2] + red[3];
        red[0] = rsqrtf(t * (1.0f / DIMM) + 1e-6f);
    }
    __syncthreads();
    float rinv = red[0];
    bf16* orow = out + (size_t)tok * DIMM;
    orow[tid]       = __float2bfloat16_rn(v0 * rinv * scale[tid]);
    orow[tid + 128] = __float2bfloat16_rn(v1 * rinv * scale[tid + 128]);
    orow[tid + 256] = __float2bfloat16_rn(v2 * rinv * scale[tid + 256]);
}

// ---------------------------------------------------------------------------
// QK rms-norm + RoPE, warp-per-token (in-place on f32 qkv)
// ---------------------------------------------------------------------------
__global__ __launch_bounds__(128)
void qkrope_kernel(float* __restrict__ qkv,
                   const float* __restrict__ nq,
                   const float* __restrict__ nk,
                   const float* __restrict__ cosT,
                   const float* __restrict__ sinT) {
    int tid = threadIdx.x;
    int lane = tid & 31;
    int tok = blockIdx.x * 4 + (tid >> 5);
    size_t base = (size_t)tok * QKVN;
    float* qp = qkv + base;
    float* kp = qkv + base + DIMM;

    float4 qv[3], kv[3];
    float ssq = 0.f, ssk = 0.f;
    #pragma unroll
    for (int i = 0; i < 3; i++) {
        int e0 = i * 128 + lane * 4;
        qv[i] = *(const float4*)(qp + e0);
        kv[i] = *(const float4*)(kp + e0);
        ssq += qv[i].x*qv[i].x + qv[i].y*qv[i].y + qv[i].z*qv[i].z + qv[i].w*qv[i].w;
        ssk += kv[i].x*kv[i].x + kv[i].y*kv[i].y + kv[i].z*kv[i].z + kv[i].w*kv[i].w;
    }
    #pragma unroll
    for (int m = 16; m >= 1; m >>= 1) {
        ssq += __shfl_xor_sync(0xffffffffu, ssq, m);
        ssk += __shfl_xor_sync(0xffffffffu, ssk, m);
    }
    float rq = rsqrtf(ssq * (1.0f / DIMM) + 1e-6f);
    float rk = rsqrtf(ssk * (1.0f / DIMM) + 1e-6f);

    int l = tok & (LL - 1);
    int j2 = 2 * (lane & 7);
    float c0 = cosT[l * 16 + j2],     s0 = sinT[l * 16 + j2];
    float c1 = cosT[l * 16 + j2 + 1], s1 = sinT[l * 16 + j2 + 1];

    #pragma unroll
    for (int i = 0; i < 3; i++) {
        int e0 = i * 128 + lane * 4;
        float4 nqv = *(const float4*)(nq + e0);
        float4 nkv = *(const float4*)(nk + e0);
        float a0 = qv[i].x * rq * nqv.x, a1 = qv[i].y * rq * nqv.y;
        float a2 = qv[i].z * rq * nqv.z, a3 = qv[i].w * rq * nqv.w;
        float4 o;
        o.x = a0 * c0 - a1 * s0;  o.y = a0 * s0 + a1 * c0;
        o.z = a2 * c1 - a3 * s1;  o.w = a2 * s1 + a3 * c1;
        *(float4*)(qp + e0) = o;
        float b0 = kv[i].x * rk * nkv.x, b1 = kv[i].y * rk * nkv.y;
        float b2 = kv[i].z * rk * nkv.z, b3 = kv[i].w * rk * nkv.w;
        float4 p;
        p.x = b0 * c0 - b1 * s0;  p.y = b0 * s0 + b1 * c0;
        p.z = b2 * c1 - b3 * s1;  p.w = b2 * s1 + b3 * c1;
        *(float4*)(kp + e0) = p;
    }
}

// ---------------------------------------------------------------------------
// Attention (single-pass softmax; scores bounded).
// MODE 0: write f32; MODE 1: += f32; MODE 2: += f32 and emit bf16 total.
// ---------------------------------------------------------------------------
template <int VAR>
__device__ __forceinline__ int tok_of(int g, int s) {
    if (VAR == 0) { int b = g >> 7, t = g & 127; return b * LL + t * FRR + s; }
    if (VAR == 1) { int b = g >> 6, fr = g & 63; return b * LL + s * FRR + fr; }
    int b = g >> 8, r = g & 255;
    int t1 = r >> 3, f1 = r & 7;
    int t2 = s >> 3, f2 = s & 7;
    return b * LL + (t1 * 4 + t2) * FRR + f1 * 8 + f2;
}

template <int VAR, int S, int MODE>
__global__ void attn_kernel(const float* __restrict__ qkv,
                            float* __restrict__ ysum,
                            bf16* __restrict__ ysb) {
    __shared__ float Ks[S][HDIM];
    __shared__ float Vs[S][HDIM];
    int g = blockIdx.x, h = blockIdx.y, tid = threadIdx.x;

    for (int idx = tid; idx < S * HDIM; idx += S) {
        int r = idx >> 5, d = idx & 31;
        size_t base = (size_t)tok_of<VAR>(g, r) * QKVN + h * HDIM;
        Ks[r][d] = qkv[base + 384 + d];
        Vs[r][d] = qkv[base + 768 + d];
    }
    size_t qbase = (size_t)tok_of<VAR>(g, tid) * QKVN + h * HDIM;
    float q[HDIM];
    #pragma unroll
    for (int d4 = 0; d4 < 8; d4++) {
        float4 v = *(const float4*)(qkv + qbase + d4 * 4);
        q[d4*4+0] = v.x; q[d4*4+1] = v.y; q[d4*4+2] = v.z; q[d4*4+3] = v.w;
    }
    __syncthreads();

    const float rscale = 0.17677669529663687f;
    float lsum = 0.f;
    float acc[HDIM];
    #pragma unroll
    for (int d = 0; d < HDIM; d++) acc[d] = 0.f;

    for (int j = 0; j < S; j++) {
        float s = 0.f;
        #pragma unroll
        for (int d = 0; d < HDIM; d++) s += q[d] * Ks[j][d];
        float p = __expf(s * rscale);
        lsum += p;
        #pragma unroll
        for (int d = 0; d < HDIM; d++) acc[d] += p * Vs[j][d];
    }
    float inv = 1.f / lsum;
    size_t obase = (size_t)tok_of<VAR>(g, tid) * DIMM + h * HDIM;
    #pragma unroll
    for (int d = 0; d < HDIM; d++) {
        if (MODE == 0)      ysum[obase + d] = acc[d] * inv;
        else if (MODE == 1) ysum[obase + d] += acc[d] * inv;
        else {
            float t = ysum[obase + d] + acc[d] * inv;
            ysum[obase + d] = t;
            ysb[obase + d] = __float2bfloat16_rn(t);
        }
    }
}

// ---------------------------------------------------------------------------
// bf16 tensor-core GEMM: C(M,N) = epi(A(M,K) @ Wt(N,K)^T + bias)
// A [M][K] bf16 row-major, Wt [N][K] bf16 (pre-transposed weights).
// 128x128x32 tile, 256 threads (8 warps 4m x 2n), warp tile 32x64.
// mma.sync.aligned.m16n8k16.row.col.f32.bf16.bf16.f32
// Both smem tiles [128][40] bf16 (k-contiguous, stride 40 -> conflict-free).
// EPI 0: f32 store; EPI 1: bf16 gelu store; EPI 2: f32 += (residual).
// ---------------------------------------------------------------------------
#define GBM 128
#define GBN 128
#define GBK 32
#define KSTR 40   // smem row stride in bf16 units

__device__ __forceinline__ float gelu_tanh(float x) {
    float c = 0.7978845608028654f;
    float t = tanhf(c * (x + 0.044715f * x * x * x));
    return 0.5f * x * (1.0f + t);
}

__device__ __forceinline__ void cp16(void* smem, const void* gmem) {
    unsigned s = (unsigned)__cvta_generic_to_shared(smem);
    asm volatile("cp.async.cg.shared.global [%0], [%1], 16;\n" :: "r"(s), "l"(gmem));
}
#define CP_COMMIT() asm volatile("cp.async.commit_group;\n" ::: "memory")
#define CP_WAIT(n)  asm volatile("cp.async.wait_group %0;\n" :: "n"(n) : "memory")

__device__ __forceinline__ void mma_bf16(float* c, const unsigned* a, const unsigned* b) {
    asm volatile(
        "mma.sync.aligned.m16n8k16.row.col.f32.bf16.bf16.f32 "
        "{%0,%1,%2,%3}, {%4,%5,%6,%7}, {%8,%9}, {%0,%1,%2,%3};\n"
        : "+f"(c[0]), "+f"(c[1]), "+f"(c[2]), "+f"(c[3])
        : "r"(a[0]), "r"(a[1]), "r"(a[2]), "r"(a[3]), "r"(b[0]), "r"(b[1]));
}

template <int EPI>
__global__ __launch_bounds__(256)
void mma_gemm(const bf16* __restrict__ A, const bf16* __restrict__ Wt,
              const float* __restrict__ bias, void* __restrict__ Cv,
              int M, int N, int K) {
    __shared__ bf16 As[2][GBM][KSTR];
    __shared__ bf16 Bs[2][GBN][KSTR];

    int tid  = threadIdx.x;
    int n0   = blockIdx.x * GBN, m0 = blockIdx.y * GBM;
    int warp = tid >> 5, lane = tid & 31;
    int gid  = lane >> 2, tid4 = lane & 3;
    int wm   = (warp & 3) * 32;
    int wn   = (warp >> 2) * 64;

    const bf16* Abase = A  + (size_t)m0 * K;
    const bf16* Bbase = Wt + (size_t)n0 * K;

    float c[2][8][4];
    #pragma unroll
    for (int mt = 0; mt < 2; mt++)
        #pragma unroll
        for (int nt = 0; nt < 8; nt++)
            #pragma unroll
            for (int r = 0; r < 4; r++) c[mt][nt][r] = 0.f;

    // per k-tile: A 128 rows x 4 chunks(8 bf16) + B 128 x 4 = 1024 chunks
    auto load_tiles = [&](int buf, int k0) {
        #pragma unroll
        for (int i = 0; i < 2; i++) {
            int ch = tid + i * 256;
            int r = ch >> 2, cc = ch & 3;
            cp16(&As[buf][r][cc * 8], Abase + (size_t)r * K + k0 + cc * 8);
            cp16(&Bs[buf][r][cc * 8], Bbase + (size_t)r * K + k0 + cc * 8);
        }
    };

    int kTiles = K / GBK;
    load_tiles(0, 0);
    CP_COMMIT();

    for (int kt = 0; kt < kTiles; kt++) {
        int buf = kt & 1;
        if (kt + 1 < kTiles) {
            load_tiles(buf ^ 1, (kt + 1) * GBK);
            CP_COMMIT();
            CP_WAIT(1);
        } else {
            CP_WAIT(0);
        }
        __syncthreads();

        #pragma unroll
        for (int ks = 0; ks < GBK; ks += 16) {
            unsigned af[2][4], bf[8][2];
            int kk = ks + 2 * tid4;
            #pragma unroll
            for (int mt = 0; mt < 2; mt++) {
                int r = wm + mt * 16 + gid;
                af[mt][0] = *(const unsigned*)&As[buf][r][kk];
                af[mt][1] = *(const unsigned*)&As[buf][r + 8][kk];
                af[mt][2] = *(const unsigned*)&As[buf][r][kk + 8];
                af[mt][3] = *(const unsigned*)&As[buf][r + 8][kk + 8];
            }
            #pragma unroll
            for (int nt = 0; nt < 8; nt++) {
                int nr = wn + nt * 8 + gid;
                bf[nt][0] = *(const unsigned*)&Bs[buf][nr][kk];
                bf[nt][1] = *(const unsigned*)&Bs[buf][nr][kk + 8];
            }
            #pragma unroll
            for (int mt = 0; mt < 2; mt++)
                #pragma unroll
                for (int nt = 0; nt < 8; nt++)
                    mma_bf16(c[mt][nt], af[mt], bf[nt]);
        }
        __syncthreads();
    }

    #pragma unroll
    for (int mt = 0; mt < 2; mt++) {
        int r0 = m0 + wm + mt * 16 + gid;
        int r1 = r0 + 8;
        #pragma unroll
        for (int nt = 0; nt < 8; nt++) {
            int cc = n0 + wn + nt * 8 + 2 * tid4;
            float b0 = bias[cc], b1 = bias[cc + 1];
            float v00 = c[mt][nt][0] + b0, v01 = c[mt][nt][1] + b1;
            float v10 = c[mt][nt][2] + b0, v11 = c[mt][nt][3] + b1;
            if (EPI == 0) {
                float* C = (float*)Cv;
                *(float2*)(C + (size_t)r0 * N + cc) = make_float2(v00, v01);
                *(float2*)(C + (size_t)r1 * N + cc) = make_float2(v10, v11);
            } else if (EPI == 1) {
                bf16* C = (bf16*)Cv;
                *(bf162*)(C + (size_t)r0 * N + cc) =
                    __floats2bfloat162_rn(gelu_tanh(v00), gelu_tanh(v01));
                *(bf162*)(C + (size_t)r1 * N + cc) =
                    __floats2bfloat162_rn(gelu_tanh(v10), gelu_tanh(v11));
            } else {
                float* C = (float*)Cv;
                float* p0 = C + (size_t)r0 * N + cc;
                float* p1 = C + (size_t)r1 * N + cc;
                float2 o0 = *(float2*)p0, o1 = *(float2*)p1;
                *(float2*)p0 = make_float2(o0.x + v00, o0.y + v01);
                *(float2*)p1 = make_float2(o1.x + v10, o1.y + v11);
            }
        }
    }
}

// ---------------------------------------------------------------------------
// kernel_launch
// ---------------------------------------------------------------------------
extern "C" void kernel_launch(void* const* d_in, const int* in_sizes, int n_in,
                              void* d_out, int out_size) {
    const float* x      = (const float*)d_in[0];
    const float* cosT   = (const float*)d_in[1];
    const float* sinT   = (const float*)d_in[2];
    const float* qkv_w  = (const float*)d_in[3];
    const float* qkv_b  = (const float*)d_in[4];
    const float* nq_s   = (const float*)d_in[5];
    const float* nk_s   = (const float*)d_in[6];
    const float* proj_w = (const float*)d_in[7];
    const float* proj_b = (const float*)d_in[8];
    const float* n1_s   = (const float*)d_in[9];
    const float* n2_s   = (const float*)d_in[10];
    const float* w1     = (const float*)d_in[11];
    const float* b1     = (const float*)d_in[12];
    const float* w2     = (const float*)d_in[13];
    const float* b2     = (const float*)d_in[14];
    float* out = (float*)d_out;

    float *xs, *qkv, *ysum;
    bf16 *xnb, *ysb, *hb, *h1b, *wq, *wp, *ww1, *ww2;
    cudaGetSymbolAddress((void**)&xs,   g_xs);
    cudaGetSymbolAddress((void**)&xnb,  g_xnb);
    cudaGetSymbolAddress((void**)&qkv,  g_qkv);
    cudaGetSymbolAddress((void**)&ysum, g_ysum);
    cudaGetSymbolAddress((void**)&ysb,  g_ysb);
    cudaGetSymbolAddress((void**)&hb,   g_hb);
    cudaGetSymbolAddress((void**)&h1b,  g_h1b);
    cudaGetSymbolAddress((void**)&wq,   g_wqkv);
    cudaGetSymbolAddress((void**)&wp,   g_wproj);
    cudaGetSymbolAddress((void**)&ww1,  g_w1);
    cudaGetSymbolAddress((void**)&ww2,  g_w2);

    dim3 tb(32, 8);

    // weight prep: transpose + bf16 (w [K][N] -> wt [N][K])
    wprep_kernel<<<dim3(QKVN/32, DIMM/32), tb>>>(qkv_w, wq, DIMM, QKVN);
    wprep_kernel<<<dim3(DIMM/32, DIMM/32), tb>>>(proj_w, wp, DIMM, DIMM);
    wprep_kernel<<<dim3(FFN/32,  DIMM/32), tb>>>(w1, ww1, DIMM, FFN);
    wprep_kernel<<<dim3(DIMM/32, FFN/32),  tb>>>(w2, ww2, FFN, DIMM);

    // fused transpose + rms1
    fuse_in_kernel<<<dim3(LL/16, BB), 256>>>(x, n1_s, xs, xnb);

    // qkv = xnb @ wq^T + qkv_b  (f32 out)
    mma_gemm<0><<<dim3(QKVN/GBN, NTOK/GBM), 256>>>(xnb, wq, qkv_b,
                                                   qkv, NTOK, QKVN, DIMM);

    // q/k rmsnorm + rope
    qkrope_kernel<<<NTOK/4, 128>>>(qkv, nq_s, nk_s, cosT, sinT);

    // three attentions
    attn_kernel<0, 64,  0><<<dim3(BB * TT,  NHEAD), 64 >>>(qkv, ysum, ysb);
    attn_kernel<1, 128, 1><<<dim3(BB * FRR, NHEAD), 128>>>(qkv, ysum, ysb);
    attn_kernel<2, 32,  2><<<dim3(BB * 256, NHEAD), 32 >>>(qkv, ysum, ysb);

    // xs += ysb @ wp^T + proj_b
    mma_gemm<2><<<dim3(DIMM/GBN, NTOK/GBM), 256>>>(ysb, wp, proj_b,
                                                   xs, NTOK, DIMM, DIMM);

    // hb = bf16(rms(xs, n2))
    rms_kernel<<<NTOK, 128>>>(xs, n2_s, hb);

    // h1b = bf16(gelu(hb @ ww1^T + b1))
    mma_gemm<1><<<dim3(FFN/GBN, NTOK/GBM), 256>>>(hb, ww1, b1,
                                                  h1b, NTOK, FFN, DIMM);

    // xs += h1b @ ww2^T + b2
    mma_gemm<2><<<dim3(DIMM/GBN, NTOK/GBM), 256>>>(h1b, ww2, b2,
                                                   xs, NTOK, DIMM, FFN);

    // xs -> out
    transpose_kernel<<<dim3(DIMM/32, LL/32, BB), tb>>>(xs, out, LL, DIMM);
}

// round 8
// speedup vs baseline: 2.7213x; 1.1039x over previous
#include <cuda_runtime.h>
#include <cuda_bf16.h>
#include <math.h>

#define BB    4
#define TT    128
#define FRR   64
#define LL    8192
#define DIMM  384
#define NHEAD 12
#define HDIM  32
#define NTOK  (BB*LL)
#define QKVN  (3*DIMM)
#define FFN   (4*DIMM)

typedef __nv_bfloat16  bf16;
typedef __nv_bfloat162 bf162;

// ---------------------------------------------------------------------------
// Scratch
// ---------------------------------------------------------------------------
__device__ float g_xs  [(size_t)NTOK * DIMM];
__device__ bf16  g_xnb [(size_t)NTOK * DIMM];
__device__ float g_qkv [(size_t)NTOK * QKVN];
__device__ float g_ysum[(size_t)NTOK * DIMM];
__device__ bf16  g_ysb [(size_t)NTOK * DIMM];
__device__ bf16  g_hb  [(size_t)NTOK * DIMM];
__device__ bf16  g_h1b [(size_t)NTOK * FFN];
__device__ bf16  g_wqkv [QKVN * DIMM];
__device__ bf16  g_wproj[DIMM * DIMM];
__device__ bf16  g_w1   [FFN * DIMM];
__device__ bf16  g_w2   [DIMM * FFN];

// ---------------------------------------------------------------------------
// Weight prep: w [K][N] f32 -> wt [N][K] bf16
// ---------------------------------------------------------------------------
__global__ void wprep_kernel(const float* __restrict__ w,
                             bf16* __restrict__ wt, int K, int N) {
    __shared__ float tile[32][33];
    int n0 = blockIdx.x * 32, k0 = blockIdx.y * 32;
    int tx = threadIdx.x, ty = threadIdx.y;
    #pragma unroll
    for (int i = 0; i < 32; i += 8)
        tile[ty + i][tx] = w[(size_t)(k0 + ty + i) * N + n0 + tx];
    __syncthreads();
    #pragma unroll
    for (int i = 0; i < 32; i += 8)
        wt[(size_t)(n0 + ty + i) * K + k0 + tx] =
            __float2bfloat16_rn(tile[tx][ty + i]);
}

// ---------------------------------------------------------------------------
// Fused input transpose + rms1
// ---------------------------------------------------------------------------
__global__ __launch_bounds__(256)
void fuse_in_kernel(const float* __restrict__ x,
                    const float* __restrict__ n1,
                    float* __restrict__ xs, bf16* __restrict__ xnb) {
    __shared__ float tile[DIMM][17];
    __shared__ float rinv[16];
    int tid = threadIdx.x;
    int l0 = blockIdx.x * 16;
    int b  = blockIdx.y;
    const float* xb = x + (size_t)b * DIMM * LL + l0;

    #pragma unroll
    for (int it = 0; it < 24; it++) {
        int idx = tid + it * 256;
        int d = idx >> 4, c = idx & 15;
        tile[d][c] = xb[(size_t)d * LL + c];
    }
    __syncthreads();

    int tok = tid >> 4, j = tid & 15;
    float s = 0.f;
    #pragma unroll
    for (int k = 0; k < 24; k++) {
        float v = tile[j + 16 * k][tok];
        s += v * v;
    }
    #pragma unroll
    for (int m = 8; m >= 1; m >>= 1)
        s += __shfl_xor_sync(0xffffffffu, s, m);
    if (j == 0) rinv[tok] = rsqrtf(s * (1.0f / DIMM) + 1e-6f);
    __syncthreads();

    size_t gbase = ((size_t)b * LL + l0) * DIMM;
    #pragma unroll
    for (int it = 0; it < 24; it++) {
        int idx = tid + it * 256;
        int t2 = idx / DIMM, d = idx - t2 * DIMM;
        float raw = tile[d][t2];
        xs[gbase + (size_t)t2 * DIMM + d] = raw;
        xnb[gbase + (size_t)t2 * DIMM + d] =
            __float2bfloat16_rn(raw * rinv[t2] * n1[d]);
    }
}

// ---------------------------------------------------------------------------
// Output transpose
// ---------------------------------------------------------------------------
__global__ void transpose_kernel(const float* __restrict__ in,
                                 float* __restrict__ out,
                                 int rows, int cols) {
    __shared__ float tile[32][33];
    int bx = blockIdx.x * 32;
    int by = blockIdx.y * 32;
    size_t plane = (size_t)rows * cols;
    const float* inb = in + (size_t)blockIdx.z * plane;
    float* outb      = out + (size_t)blockIdx.z * plane;
    int tx = threadIdx.x, ty = threadIdx.y;
    #pragma unroll
    for (int i = 0; i < 32; i += 8)
        tile[ty + i][tx] = inb[(size_t)(by + ty + i) * cols + bx + tx];
    __syncthreads();
    #pragma unroll
    for (int i = 0; i < 32; i += 8)
        outb[(size_t)(bx + ty + i) * rows + by + tx] = tile[tx][ty + i];
}

// ---------------------------------------------------------------------------
// rms2
// ---------------------------------------------------------------------------
__global__ void rms_kernel(const float* __restrict__ in,
                           const float* __restrict__ scale,
                           bf16* __restrict__ out) {
    int tok = blockIdx.x;
    int tid = threadIdx.x;
    const float* row = in + (size_t)tok * DIMM;
    float v0 = row[tid], v1 = row[tid + 128], v2 = row[tid + 256];
    float s = v0*v0 + v1*v1 + v2*v2;
    #pragma unroll
    for (int off = 16; off > 0; off >>= 1)
        s += __shfl_down_sync(0xffffffffu, s, off);
    __shared__ float red[4];
    if ((tid & 31) == 0) red[tid >> 5] = s;
    __syncthreads();
    if (tid == 0) {
        float t = red[0] + red[1] + red[2] + red[3];
        red[0] = rsqrtf(t * (1.0f / DIMM) + 1e-6f);
    }
    __syncthreads();
    float rinv = red[0];
    bf16* orow = out + (size_t)tok * DIMM;
    orow[tid]       = __float2bfloat16_rn(v0 * rinv * scale[tid]);
    orow[tid + 128] = __float2bfloat16_rn(v1 * rinv * scale[tid + 128]);
    orow[tid + 256] = __float2bfloat16_rn(v2 * rinv * scale[tid + 256]);
}

// ---------------------------------------------------------------------------
// QK rms-norm + RoPE
// ---------------------------------------------------------------------------
__global__ __launch_bounds__(128)
void qkrope_kernel(float* __restrict__ qkv,
                   const float* __restrict__ nq,
                   const float* __restrict__ nk,
                   const float* __restrict__ cosT,
                   const float* __restrict__ sinT) {
    int tid = threadIdx.x;
    int lane = tid & 31;
    int tok = blockIdx.x * 4 + (tid >> 5);
    size_t base = (size_t)tok * QKVN;
    float* qp = qkv + base;
    float* kp = qkv + base + DIMM;

    float4 qv[3], kv[3];
    float ssq = 0.f, ssk = 0.f;
    #pragma unroll
    for (int i = 0; i < 3; i++) {
        int e0 = i * 128 + lane * 4;
        qv[i] = *(const float4*)(qp + e0);
        kv[i] = *(const float4*)(kp + e0);
        ssq += qv[i].x*qv[i].x + qv[i].y*qv[i].y + qv[i].z*qv[i].z + qv[i].w*qv[i].w;
        ssk += kv[i].x*kv[i].x + kv[i].y*kv[i].y + kv[i].z*kv[i].z + kv[i].w*kv[i].w;
    }
    #pragma unroll
    for (int m = 16; m >= 1; m >>= 1) {
        ssq += __shfl_xor_sync(0xffffffffu, ssq, m);
        ssk += __shfl_xor_sync(0xffffffffu, ssk, m);
    }
    float rq = rsqrtf(ssq * (1.0f / DIMM) + 1e-6f);
    float rk = rsqrtf(ssk * (1.0f / DIMM) + 1e-6f);

    int l = tok & (LL - 1);
    int j2 = 2 * (lane & 7);
    float c0 = cosT[l * 16 + j2],     s0 = sinT[l * 16 + j2];
    float c1 = cosT[l * 16 + j2 + 1], s1 = sinT[l * 16 + j2 + 1];

    #pragma unroll
    for (int i = 0; i < 3; i++) {
        int e0 = i * 128 + lane * 4;
        float4 nqv = *(const float4*)(nq + e0);
        float4 nkv = *(const float4*)(nk + e0);
        float a0 = qv[i].x * rq * nqv.x, a1 = qv[i].y * rq * nqv.y;
        float a2 = qv[i].z * rq * nqv.z, a3 = qv[i].w * rq * nqv.w;
        float4 o;
        o.x = a0 * c0 - a1 * s0;  o.y = a0 * s0 + a1 * c0;
        o.z = a2 * c1 - a3 * s1;  o.w = a2 * s1 + a3 * c1;
        *(float4*)(qp + e0) = o;
        float b0 = kv[i].x * rk * nkv.x, b1 = kv[i].y * rk * nkv.y;
        float b2 = kv[i].z * rk * nkv.z, b3 = kv[i].w * rk * nkv.w;
        float4 p;
        p.x = b0 * c0 - b1 * s0;  p.y = b0 * s0 + b1 * c0;
        p.z = b2 * c1 - b3 * s1;  p.w = b2 * s1 + b3 * c1;
        *(float4*)(kp + e0) = p;
    }
}

// ---------------------------------------------------------------------------
// Attention (single-pass softmax)
// ---------------------------------------------------------------------------
template <int VAR>
__device__ __forceinline__ int tok_of(int g, int s) {
    if (VAR == 0) { int b = g >> 7, t = g & 127; return b * LL + t * FRR + s; }
    if (VAR == 1) { int b = g >> 6, fr = g & 63; return b * LL + s * FRR + fr; }
    int b = g >> 8, r = g & 255;
    int t1 = r >> 3, f1 = r & 7;
    int t2 = s >> 3, f2 = s & 7;
    return b * LL + (t1 * 4 + t2) * FRR + f1 * 8 + f2;
}

template <int VAR, int S, int MODE>
__global__ void attn_kernel(const float* __restrict__ qkv,
                            float* __restrict__ ysum,
                            bf16* __restrict__ ysb) {
    __shared__ float Ks[S][HDIM];
    __shared__ float Vs[S][HDIM];
    int g = blockIdx.x, h = blockIdx.y, tid = threadIdx.x;

    for (int idx = tid; idx < S * HDIM; idx += S) {
        int r = idx >> 5, d = idx & 31;
        size_t base = (size_t)tok_of<VAR>(g, r) * QKVN + h * HDIM;
        Ks[r][d] = qkv[base + 384 + d];
        Vs[r][d] = qkv[base + 768 + d];
    }
    size_t qbase = (size_t)tok_of<VAR>(g, tid) * QKVN + h * HDIM;
    float q[HDIM];
    #pragma unroll
    for (int d4 = 0; d4 < 8; d4++) {
        float4 v = *(const float4*)(qkv + qbase + d4 * 4);
        q[d4*4+0] = v.x; q[d4*4+1] = v.y; q[d4*4+2] = v.z; q[d4*4+3] = v.w;
    }
    __syncthreads();

    const float rscale = 0.17677669529663687f;
    float lsum = 0.f;
    float acc[HDIM];
    #pragma unroll
    for (int d = 0; d < HDIM; d++) acc[d] = 0.f;

    for (int j = 0; j < S; j++) {
        float s = 0.f;
        #pragma unroll
        for (int d = 0; d < HDIM; d++) s += q[d] * Ks[j][d];
        float p = __expf(s * rscale);
        lsum += p;
        #pragma unroll
        for (int d = 0; d < HDIM; d++) acc[d] += p * Vs[j][d];
    }
    float inv = 1.f / lsum;
    size_t obase = (size_t)tok_of<VAR>(g, tid) * DIMM + h * HDIM;
    #pragma unroll
    for (int d = 0; d < HDIM; d++) {
        if (MODE == 0)      ysum[obase + d] = acc[d] * inv;
        else if (MODE == 1) ysum[obase + d] += acc[d] * inv;
        else {
            float t = ysum[obase + d] + acc[d] * inv;
            ysum[obase + d] = t;
            ysb[obase + d] = __float2bfloat16_rn(t);
        }
    }
}

// ---------------------------------------------------------------------------
// bf16 tensor-core GEMM with ldmatrix fragments, GBK=64, dynamic smem.
// C(M,N) = epi(A(M,K) @ Wt(N,K)^T + bias)
// 128x128x64 tile, 256 threads (8 warps 4m x 2n), warp tile 32x64.
// smem tiles [128][72] bf16 (stride 72 -> ldmatrix conflict-free).
// EPI 0: f32 store; EPI 1: bf16 gelu store; EPI 2: f32 +=.
// ---------------------------------------------------------------------------
#define GBM 128
#define GBN 128
#define GBK 64
#define KSTR 72
#define ATILE (2 * GBM * KSTR)                       // bf16 elems, both buffers
#define GEMM_SMEM_BYTES (2 * ATILE * 2)              // A + B, bytes

__device__ __forceinline__ float gelu_tanh(float x) {
    float c = 0.7978845608028654f;
    float t = tanhf(c * (x + 0.044715f * x * x * x));
    return 0.5f * x * (1.0f + t);
}

__device__ __forceinline__ void cp16(void* smem, const void* gmem) {
    unsigned s = (unsigned)__cvta_generic_to_shared(smem);
    asm volatile("cp.async.cg.shared.global [%0], [%1], 16;\n" :: "r"(s), "l"(gmem));
}
#define CP_COMMIT() asm volatile("cp.async.commit_group;\n" ::: "memory")
#define CP_WAIT(n)  asm volatile("cp.async.wait_group %0;\n" :: "n"(n) : "memory")

__device__ __forceinline__ void ldsm4(unsigned& r0, unsigned& r1,
                                      unsigned& r2, unsigned& r3, unsigned addr) {
    asm volatile("ldmatrix.sync.aligned.m8n8.x4.shared.b16 {%0,%1,%2,%3}, [%4];\n"
                 : "=r"(r0), "=r"(r1), "=r"(r2), "=r"(r3) : "r"(addr));
}

__device__ __forceinline__ void mma_bf16(float* c, const unsigned* a, const unsigned* b) {
    asm volatile(
        "mma.sync.aligned.m16n8k16.row.col.f32.bf16.bf16.f32 "
        "{%0,%1,%2,%3}, {%4,%5,%6,%7}, {%8,%9}, {%0,%1,%2,%3};\n"
        : "+f"(c[0]), "+f"(c[1]), "+f"(c[2]), "+f"(c[3])
        : "r"(a[0]), "r"(a[1]), "r"(a[2]), "r"(a[3]), "r"(b[0]), "r"(b[1]));
}

template <int EPI>
__global__ __launch_bounds__(256)
void mma_gemm(const bf16* __restrict__ A, const bf16* __restrict__ Wt,
              const float* __restrict__ bias, void* __restrict__ Cv,
              int M, int N, int K) {
    extern __shared__ char dynsmem[];
    bf16* As = (bf16*)dynsmem;                    // [2][GBM][KSTR]
    bf16* Bs = (bf16*)(dynsmem + ATILE * 2);      // [2][GBN][KSTR]

    int tid  = threadIdx.x;
    int n0   = blockIdx.x * GBN, m0 = blockIdx.y * GBM;
    int warp = tid >> 5, lane = tid & 31;
    int wm   = (warp & 3) * 32;
    int wn   = (warp >> 2) * 64;

    const bf16* Abase = A  + (size_t)m0 * K;
    const bf16* Bbase = Wt + (size_t)n0 * K;

    // ldmatrix per-lane address pieces
    int mrow = lane & 7;
    int sel  = lane >> 3;              // 0..3
    int a_row_add = (sel & 1) * 8 + mrow;
    int a_k_add   = (sel >> 1) * 8;
    int b_row_add = (sel >> 1) * 8 + mrow;
    int b_k_add   = (sel & 1) * 8;

    unsigned As_u = (unsigned)__cvta_generic_to_shared(As);
    unsigned Bs_u = (unsigned)__cvta_generic_to_shared(Bs);

    float c[2][8][4];
    #pragma unroll
    for (int mt = 0; mt < 2; mt++)
        #pragma unroll
        for (int nt = 0; nt < 8; nt++)
            #pragma unroll
            for (int r = 0; r < 4; r++) c[mt][nt][r] = 0.f;

    auto load_tiles = [&](int buf, int k0) {
        bf16* Ad = As + buf * GBM * KSTR;
        bf16* Bd = Bs + buf * GBN * KSTR;
        #pragma unroll
        for (int i = 0; i < 4; i++) {
            int ch = tid + i * 256;
            int r = ch >> 3, cc = ch & 7;
            cp16(Ad + r * KSTR + cc * 8, Abase + (size_t)r * K + k0 + cc * 8);
            cp16(Bd + r * KSTR + cc * 8, Bbase + (size_t)r * K + k0 + cc * 8);
        }
    };

    int kTiles = K / GBK;
    load_tiles(0, 0);
    CP_COMMIT();

    for (int kt = 0; kt < kTiles; kt++) {
        int buf = kt & 1;
        if (kt + 1 < kTiles) {
            load_tiles(buf ^ 1, (kt + 1) * GBK);
            CP_COMMIT();
            CP_WAIT(1);
        } else {
            CP_WAIT(0);
        }
        __syncthreads();

        unsigned Abuf = As_u + (unsigned)(buf * GBM * KSTR) * 2;
        unsigned Bbuf = Bs_u + (unsigned)(buf * GBN * KSTR) * 2;

        #pragma unroll
        for (int ks = 0; ks < GBK; ks += 16) {
            unsigned af[2][4], bf[8][2];
            #pragma unroll
            for (int mt = 0; mt < 2; mt++) {
                unsigned addr = Abuf +
                    (unsigned)((wm + mt * 16 + a_row_add) * KSTR + ks + a_k_add) * 2;
                ldsm4(af[mt][0], af[mt][1], af[mt][2], af[mt][3], addr);
            }
            #pragma unroll
            for (int np = 0; np < 4; np++) {
                unsigned addr = Bbuf +
                    (unsigned)((wn + np * 16 + b_row_add) * KSTR + ks + b_k_add) * 2;
                ldsm4(bf[2*np][0], bf[2*np][1], bf[2*np+1][0], bf[2*np+1][1], addr);
            }
            #pragma unroll
            for (int mt = 0; mt < 2; mt++)
                #pragma unroll
                for (int nt = 0; nt < 8; nt++)
                    mma_bf16(c[mt][nt], af[mt], bf[nt]);
        }
        __syncthreads();
    }

    int gid  = lane >> 2, tid4 = lane & 3;
    #pragma unroll
    for (int mt = 0; mt < 2; mt++) {
        int r0 = m0 + wm + mt * 16 + gid;
        int r1 = r0 + 8;
        #pragma unroll
        for (int nt = 0; nt < 8; nt++) {
            int cc = n0 + wn + nt * 8 + 2 * tid4;
            float b0 = bias[cc], b1 = bias[cc + 1];
            float v00 = c[mt][nt][0] + b0, v01 = c[mt][nt][1] + b1;
            float v10 = c[mt][nt][2] + b0, v11 = c[mt][nt][3] + b1;
            if (EPI == 0) {
                float* C = (float*)Cv;
                *(float2*)(C + (size_t)r0 * N + cc) = make_float2(v00, v01);
                *(float2*)(C + (size_t)r1 * N + cc) = make_float2(v10, v11);
            } else if (EPI == 1) {
                bf16* C = (bf16*)Cv;
                *(bf162*)(C + (size_t)r0 * N + cc) =
                    __floats2bfloat162_rn(gelu_tanh(v00), gelu_tanh(v01));
                *(bf162*)(C + (size_t)r1 * N + cc) =
                    __floats2bfloat162_rn(gelu_tanh(v10), gelu_tanh(v11));
            } else {
                float* C = (float*)Cv;
                float* p0 = C + (size_t)r0 * N + cc;
                float* p1 = C + (size_t)r1 * N + cc;
                float2 o0 = *(float2*)p0, o1 = *(float2*)p1;
                *(float2*)p0 = make_float2(o0.x + v00, o0.y + v01);
                *(float2*)p1 = make_float2(o1.x + v10, o1.y + v11);
            }
        }
    }
}

// ---------------------------------------------------------------------------
// kernel_launch
// ---------------------------------------------------------------------------
extern "C" void kernel_launch(void* const* d_in, const int* in_sizes, int n_in,
                              void* d_out, int out_size) {
    const float* x      = (const float*)d_in[0];
    const float* cosT   = (const float*)d_in[1];
    const float* sinT   = (const float*)d_in[2];
    const float* qkv_w  = (const float*)d_in[3];
    const float* qkv_b  = (const float*)d_in[4];
    const float* nq_s   = (const float*)d_in[5];
    const float* nk_s   = (const float*)d_in[6];
    const float* proj_w = (const float*)d_in[7];
    const float* proj_b = (const float*)d_in[8];
    const float* n1_s   = (const float*)d_in[9];
    const float* n2_s   = (const float*)d_in[10];
    const float* w1     = (const float*)d_in[11];
    const float* b1     = (const float*)d_in[12];
    const float* w2     = (const float*)d_in[13];
    const float* b2     = (const float*)d_in[14];
    float* out = (float*)d_out;

    float *xs, *qkv, *ysum;
    bf16 *xnb, *ysb, *hb, *h1b, *wq, *wp, *ww1, *ww2;
    cudaGetSymbolAddress((void**)&xs,   g_xs);
    cudaGetSymbolAddress((void**)&xnb,  g_xnb);
    cudaGetSymbolAddress((void**)&qkv,  g_qkv);
    cudaGetSymbolAddress((void**)&ysum, g_ysum);
    cudaGetSymbolAddress((void**)&ysb,  g_ysb);
    cudaGetSymbolAddress((void**)&hb,   g_hb);
    cudaGetSymbolAddress((void**)&h1b,  g_h1b);
    cudaGetSymbolAddress((void**)&wq,   g_wqkv);
    cudaGetSymbolAddress((void**)&wp,   g_wproj);
    cudaGetSymbolAddress((void**)&ww1,  g_w1);
    cudaGetSymbolAddress((void**)&ww2,  g_w2);

    // allow >48KB dynamic smem (host-side attr, capture-safe, idempotent)
    cudaFuncSetAttribute(mma_gemm<0>, cudaFuncAttributeMaxDynamicSharedMemorySize, GEMM_SMEM_BYTES);
    cudaFuncSetAttribute(mma_gemm<1>, cudaFuncAttributeMaxDynamicSharedMemorySize, GEMM_SMEM_BYTES);
    cudaFuncSetAttribute(mma_gemm<2>, cudaFuncAttributeMaxDynamicSharedMemorySize, GEMM_SMEM_BYTES);

    dim3 tb(32, 8);

    // weight prep
    wprep_kernel<<<dim3(QKVN/32, DIMM/32), tb>>>(qkv_w, wq, DIMM, QKVN);
    wprep_kernel<<<dim3(DIMM/32, DIMM/32), tb>>>(proj_w, wp, DIMM, DIMM);
    wprep_kernel<<<dim3(FFN/32,  DIMM/32), tb>>>(w1, ww1, DIMM, FFN);
    wprep_kernel<<<dim3(DIMM/32, FFN/32),  tb>>>(w2, ww2, FFN, DIMM);

    // fused transpose + rms1
    fuse_in_kernel<<<dim3(LL/16, BB), 256>>>(x, n1_s, xs, xnb);

    // qkv = xnb @ wq^T + qkv_b
    mma_gemm<0><<<dim3(QKVN/GBN, NTOK/GBM), 256, GEMM_SMEM_BYTES>>>(
        xnb, wq, qkv_b, qkv, NTOK, QKVN, DIMM);

    // q/k rmsnorm + rope
    qkrope_kernel<<<NTOK/4, 128>>>(qkv, nq_s, nk_s, cosT, sinT);

    // three attentions
    attn_kernel<0, 64,  0><<<dim3(BB * TT,  NHEAD), 64 >>>(qkv, ysum, ysb);
    attn_kernel<1, 128, 1><<<dim3(BB * FRR, NHEAD), 128>>>(qkv, ysum, ysb);
    attn_kernel<2, 32,  2><<<dim3(BB * 256, NHEAD), 32 >>>(qkv, ysum, ysb);

    // xs += ysb @ wp^T + proj_b
    mma_gemm<2><<<dim3(DIMM/GBN, NTOK/GBM), 256, GEMM_SMEM_BYTES>>>(
        ysb, wp, proj_b, xs, NTOK, DIMM, DIMM);

    // hb = bf16(rms(xs, n2))
    rms_kernel<<<NTOK, 128>>>(xs, n2_s, hb);

    // h1b = bf16(gelu(hb @ ww1^T + b1))
    mma_gemm<1><<<dim3(FFN/GBN, NTOK/GBM), 256, GEMM_SMEM_BYTES>>>(
        hb, ww1, b1, h1b, NTOK, FFN, DIMM);

    // xs += h1b @ ww2^T + b2
    mma_gemm<2><<<dim3(DIMM/GBN, NTOK/GBM), 256, GEMM_SMEM_BYTES>>>(
        h1b, ww2, b2, xs, NTOK, DIMM, FFN);

    // xs -> out
    transpose_kernel<<<dim3(DIMM/32, LL/32, BB), tb>>>(xs, out, LL, DIMM);
}